// round 15
// baseline (speedup 1.0000x reference)
#include <cuda_runtime.h>
#include <cuda.h>
#include <cuda_fp16.h>
#include <math.h>
#include <stdint.h>
#include <dlfcn.h>

// ---------------- problem constants ----------------
namespace hk {
constexpr int B  = 2;
constexpr int S  = 2048;
constexpr int D  = 2048;
constexpr int H  = 16;
constexpr int HD = 128;
constexpr int F  = 8192;
constexpr int BS = B * S;                     // 4096 rows
constexpr size_t NBSD = (size_t)BS * D;       // 8,388,608
constexpr size_t NBSF = (size_t)BS * F;       // 33,554,432
constexpr size_t NDD  = (size_t)D * D;
constexpr size_t NDF  = (size_t)D * F;
constexpr size_t NGW  = (size_t)H * HD * HD;  // 262,144
}

constexpr int SC_NC = 16;                      // scan chunks
constexpr int SC_L  = hk::S / SC_NC;           // 128 steps per chunk

// ---------------- scratch: fp32 intermediates ----------------
__device__ float g_resid [hk::NBSD];
__device__ float g_hend  [hk::B * hk::D * SC_NC];
__device__ float g_aend  [hk::B * hk::D * SC_NC];
__device__ float g_carry [hk::B * hk::D * SC_NC];

// ---------------- scratch: fp16 activations ----------------
__device__ __half g_omah[hk::NBSD];            // 1 - a
__device__ __half g_gbh [hk::NBSD];            // b
__device__ __half g_nA  [hk::NBSD];
__device__ __half g_yA  [hk::NBSD];
__device__ __half g_xbh [hk::NBSD];
__device__ __half g_xcH [hk::NBSD];
__device__ __half g_zA  [hk::NBSD];
__device__ __half g_n2A [hk::NBSD];
__device__ __half g_GA  [hk::NBSF];
__device__ __half g_guA [hk::NBSF];

// ---------------- scratch: fp16 transposed weights [N,K] ----------------
__device__ __half g_Wyx[2 * hk::NDD];          // [Wy ; Wx] concatenated on N
__device__ __half g_Wo[hk::NDD];
__device__ __half g_Wg[hk::NDF];
__device__ __half g_Wu[hk::NDF];
__device__ __half g_Wd[hk::NDF];
// gate weights, transposed per head [H][e][d], single fp16
__device__ __half g_aWH[hk::NGW];
__device__ __half g_iWH[hk::NGW];

// ---------------- helpers ----------------
__device__ __forceinline__ float gelu_tanh(float x) {
    float x3 = x * x * x;
    return 0.5f * x * (1.0f + tanhf(0.7978845608028654f * (x + 0.044715f * x3)));
}

__device__ __forceinline__ uint32_t s2u(const void* p) {
    uint32_t a;
    asm("{ .reg .u64 t; cvta.to.shared.u64 t, %1; cvt.u32.u64 %0, t; }" : "=r"(a) : "l"(p));
    return a;
}

__device__ __forceinline__ void ldmx4(uint32_t* r, uint32_t a) {
    asm volatile("ldmatrix.sync.aligned.m8n8.x4.shared.b16 {%0,%1,%2,%3}, [%4];"
                 : "=r"(r[0]), "=r"(r[1]), "=r"(r[2]), "=r"(r[3]) : "r"(a));
}

__device__ __forceinline__ void mma16816(float* c, const uint32_t* a, const uint32_t* b) {
    asm volatile(
        "mma.sync.aligned.m16n8k16.row.col.f32.f16.f16.f32 "
        "{%0,%1,%2,%3}, {%4,%5,%6,%7}, {%8,%9}, {%0,%1,%2,%3};"
        : "+f"(c[0]), "+f"(c[1]), "+f"(c[2]), "+f"(c[3])
        : "r"(a[0]), "r"(a[1]), "r"(a[2]), "r"(a[3]), "r"(b[0]), "r"(b[1]));
}

__device__ __forceinline__ void mbar_init(uint32_t mbar, uint32_t cnt) {
    asm volatile("mbarrier.init.shared.b64 [%0], %1;" :: "r"(mbar), "r"(cnt) : "memory");
}

__device__ __forceinline__ void mbar_expect_tx(uint32_t mbar, uint32_t bytes) {
    asm volatile("mbarrier.arrive.expect_tx.shared.b64 _, [%0], %1;"
                 :: "r"(mbar), "r"(bytes) : "memory");
}

__device__ __forceinline__ void mbar_wait(uint32_t mbar, uint32_t phase) {
    asm volatile(
        "{\n\t.reg .pred P;\n\t"
        "WAIT_%=:\n\t"
        "mbarrier.try_wait.parity.shared.b64 P, [%0], %1, 10000000;\n\t"
        "@P bra.uni DONE_%=;\n\t"
        "bra.uni WAIT_%=;\n\t"
        "DONE_%=:\n\t}"
        :: "r"(mbar), "r"(phase) : "memory");
}

__device__ __forceinline__ void tma2d(uint32_t dst, const CUtensorMap* map,
                                      int cx, int cy, uint32_t mbar) {
    asm volatile(
        "cp.async.bulk.tensor.2d.shared::cluster.global.tile.mbarrier::complete_tx::bytes "
        "[%0], [%1, {%2, %3}], [%4];"
        :: "r"(dst), "l"(map), "r"(cx), "r"(cy), "r"(mbar) : "memory");
}

// =====================================================================
// GEMM core: 256 threads (8 warps 2x4, 64x64 warp tile), CTA tile
// 128x256, TMA loads (SW64), NINE-stage mbarrier pipeline, EIGHT
// K-blocks per __syncthreads. Numerics identical to round-12/14 winner.
// =====================================================================
constexpr int GT_NSTG  = 9;
constexpr int GT_TA    = 128 * 64;              // 8192 B A tile
constexpr int GT_TB    = 256 * 64;              // 16384 B B tile
constexpr int GT_STAGE = GT_TA + GT_TB;         // 24576 B
constexpr int GT_HDR   = 1024;
constexpr int GT_SMEM  = GT_HDR + GT_NSTG * GT_STAGE;   // 222208 B
constexpr int GT_THR   = 256;

#define GEMM_MAINLOOP(mA_, mB_)                                                   \
    const uint32_t sb    = s2u(smem);                                             \
    const uint32_t tiles = sb + GT_HDR;                                           \
    const int tid  = threadIdx.x;                                                 \
    const int lane = tid & 31;                                                    \
    const int wid  = tid >> 5;                                                    \
    const int wm   = wid >> 2;        /* 0..1 -> 64-row slab */                   \
    const int wn   = wid & 3;         /* 0..3 -> 64-col slab */                   \
    const int row0 = blockIdx.y * 128;                                            \
    const int col0 = blockIdx.x * 256;                                            \
    const int KB   = K >> 5;                                                      \
    if (tid == 0) {                                                               \
        _Pragma("unroll")                                                         \
        for (int s = 0; s < GT_NSTG; s++) mbar_init(sb + s * 8, 1);               \
    }                                                                             \
    __syncthreads();                                                              \
    uint32_t arow[4], axm[4], brow[4], bxm[4];                                    \
    _Pragma("unroll")                                                             \
    for (int im = 0; im < 4; im++) {                                              \
        int r = wm * 64 + im * 16 + (lane & 15);                                  \
        arow[im] = (uint32_t)(r * 64);                                            \
        axm[im]  = (uint32_t)((r & 6) << 3);                                      \
    }                                                                             \
    _Pragma("unroll")                                                             \
    for (int ip = 0; ip < 4; ip++) {                                              \
        int r = wn * 64 + ip * 16 + (lane & 7) + ((lane >> 4) & 1) * 8;           \
        brow[ip] = (uint32_t)(r * 64);                                            \
        bxm[ip]  = (uint32_t)((r & 6) << 3);                                      \
    }                                                                             \
    const uint32_t acol = (uint32_t)((lane >> 4) * 16);                           \
    const uint32_t bcol = (uint32_t)(((lane >> 3) & 1) * 16);                     \
    float acc[4][8][4];                                                           \
    _Pragma("unroll")                                                             \
    for (int im = 0; im < 4; im++)                                                \
        _Pragma("unroll")                                                         \
        for (int in = 0; in < 8; in++)                                            \
            _Pragma("unroll")                                                     \
            for (int q = 0; q < 4; q++) acc[im][in][q] = 0.0f;                    \
    auto issue = [&](int kb) {                                                    \
        int slot = kb % GT_NSTG;                                                  \
        uint32_t bar = sb + slot * 8;                                             \
        uint32_t st  = tiles + (uint32_t)slot * GT_STAGE;                         \
        mbar_expect_tx(bar, (uint32_t)GT_STAGE);                                  \
        tma2d(st,         &mA_, kb * 32, row0, bar);                              \
        tma2d(st + GT_TA, &mB_, kb * 32, col0, bar);                              \
    };                                                                            \
    auto compute = [&](int kb) {                                                  \
        const uint32_t sA = tiles + (uint32_t)(kb % GT_NSTG) * GT_STAGE;          \
        const uint32_t sB = sA + GT_TA;                                           \
        _Pragma("unroll")                                                         \
        for (int kk = 0; kk < 2; kk++) {                                          \
            uint32_t af[4][4], bf[8][2];                                          \
            _Pragma("unroll")                                                     \
            for (int im = 0; im < 4; im++) {                                      \
                uint32_t rest = (acol + (uint32_t)(kk * 32)) ^ axm[im];           \
                ldmx4(af[im], sA + arow[im] + rest);                              \
            }                                                                     \
            _Pragma("unroll")                                                     \
            for (int ip = 0; ip < 4; ip++) {                                      \
                uint32_t rest = (bcol + (uint32_t)(kk * 32)) ^ bxm[ip];           \
                uint32_t r4[4];                                                   \
                ldmx4(r4, sB + brow[ip] + rest);                                  \
                bf[2 * ip + 0][0] = r4[0]; bf[2 * ip + 0][1] = r4[1];             \
                bf[2 * ip + 1][0] = r4[2]; bf[2 * ip + 1][1] = r4[3];             \
            }                                                                     \
            _Pragma("unroll")                                                     \
            for (int im = 0; im < 4; im++)                                        \
                _Pragma("unroll")                                                 \
                for (int in = 0; in < 8; in++)                                    \
                    mma16816(acc[im][in], af[im], bf[in]);                        \
        }                                                                         \
    };                                                                            \
    if (tid == 0) {                                                               \
        _Pragma("unroll")                                                         \
        for (int s = 0; s < GT_NSTG - 1; s++) issue(s);                           \
    }                                                                             \
    for (int kb = 0; kb < KB; kb += 8) {                                          \
        _Pragma("unroll")                                                         \
        for (int j = 0; j < 8; j++) {                                             \
            mbar_wait(sb + ((kb + j) % GT_NSTG) * 8,                              \
                      (uint32_t)(((kb + j) / GT_NSTG) & 1));                      \
            compute(kb + j);                                                      \
        }                                                                         \
        __syncthreads();                                                          \
        if (tid == 0) {                                                           \
            _Pragma("unroll")                                                     \
            for (int j = 0; j < 8; j++)                                           \
                if (kb + GT_NSTG - 1 + j < KB) issue(kb + GT_NSTG - 1 + j);       \
        }                                                                         \
    }

// =====================================================================
// gemm_tma: EPI 2 add aux fp32 -> C fp32; 3 mul auxh fp16 -> OH fp16;
//           4 gelu -> OH fp16.
// =====================================================================
template<int EPI>
__global__ void __launch_bounds__(GT_THR, 1)
gemm_tma(const __grid_constant__ CUtensorMap mA,
         const __grid_constant__ CUtensorMap mB,
         float* __restrict__ C, const float* __restrict__ aux,
         const __half* __restrict__ auxh, __half* __restrict__ OH,
         int N, int K)
{
    extern __shared__ __align__(1024) char smem[];
    GEMM_MAINLOOP(mA, mB)

    const int gid = lane >> 2, t4 = lane & 3;
    #pragma unroll
    for (int im = 0; im < 4; im++) {
        #pragma unroll
        for (int in = 0; in < 8; in++) {
            int r = row0 + wm * 64 + im * 16 + gid;
            int c = col0 + wn * 64 + in * 8 + t4 * 2;
            #pragma unroll
            for (int half = 0; half < 2; half++) {
                int rr = r + half * 8;
                float v0 = acc[im][in][half * 2 + 0];
                float v1 = acc[im][in][half * 2 + 1];
                if (EPI == 2) {
                    float2 a2 = *reinterpret_cast<const float2*>(aux + (size_t)rr * N + c);
                    v0 += a2.x; v1 += a2.y;
                    float2 o; o.x = v0; o.y = v1;
                    *reinterpret_cast<float2*>(C + (size_t)rr * N + c) = o;
                } else if (EPI == 3) {
                    __half2 a2 = *reinterpret_cast<const __half2*>(auxh + (size_t)rr * N + c);
                    v0 *= __half2float(a2.x); v1 *= __half2float(a2.y);
                    __half2 hp; hp.x = __float2half_rn(v0); hp.y = __float2half_rn(v1);
                    *reinterpret_cast<__half2*>(OH + (size_t)rr * N + c) = hp;
                } else {   // EPI == 4: gelu
                    v0 = gelu_tanh(v0); v1 = gelu_tanh(v1);
                    __half2 hp; hp.x = __float2half_rn(v0); hp.y = __float2half_rn(v1);
                    *reinterpret_cast<__half2*>(OH + (size_t)rr * N + c) = hp;
                }
            }
        }
    }
}

// =====================================================================
// gemm_dual: combined Wy+Wx GEMM over concatenated B [2*NOUT, K].
// =====================================================================
__global__ void __launch_bounds__(GT_THR, 1)
gemm_dual(const __grid_constant__ CUtensorMap mA,
          const __grid_constant__ CUtensorMap mB,
          __half* __restrict__ O1, __half* __restrict__ O2,
          int NOUT, int K)
{
    extern __shared__ __align__(1024) char smem[];
    GEMM_MAINLOOP(mA, mB)

    const bool side = (col0 >= NOUT);
    __half* dst = side ? O2 : O1;
    const int cb0 = side ? (col0 - NOUT) : col0;

    const int gid = lane >> 2, t4 = lane & 3;
    #pragma unroll
    for (int im = 0; im < 4; im++) {
        #pragma unroll
        for (int in = 0; in < 8; in++) {
            int r = row0 + wm * 64 + im * 16 + gid;
            int c = cb0 + wn * 64 + in * 8 + t4 * 2;
            #pragma unroll
            for (int half = 0; half < 2; half++) {
                int rr = r + half * 8;
                float v0 = acc[im][in][half * 2 + 0];
                float v1 = acc[im][in][half * 2 + 1];
                if (!side) { v0 = gelu_tanh(v0); v1 = gelu_tanh(v1); }
                __half2 hp; hp.x = __float2half_rn(v0); hp.y = __float2half_rn(v1);
                *reinterpret_cast<__half2*>(dst + (size_t)rr * NOUT + c) = hp;
            }
        }
    }
}

// =====================================================================
// gate_mma (unchanged winner)
// =====================================================================
constexpr int GG_CH   = 8192;
constexpr int GG_MAT  = 4 * GG_CH;
constexpr int GG_HDR  = 1024;
constexpr int GG_ASP  = GG_HDR + GG_MAT;
constexpr int GG_BSP  = GG_HDR + 3 * GG_MAT;
constexpr int GG_SMEM = GG_BSP + 32768;       // 132096 B

__global__ void __launch_bounds__(256, 1)
gate_mma(const __grid_constant__ CUtensorMap mXh,
         const __grid_constant__ CUtensorMap mWaH,
         const __grid_constant__ CUtensorMap mWiH,
         const float* __restrict__ ab, const float* __restrict__ ib,
         const float* __restrict__ apar,
         __half* __restrict__ omah, __half* __restrict__ gbh,
         float* __restrict__ hend, float* __restrict__ aend)
{
    using namespace hk;
    extern __shared__ __align__(1024) char smem[];
    const uint32_t sb    = s2u(smem);
    const uint32_t tiles = sb + GG_HDR;

    const int tid  = threadIdx.x;
    const int lane = tid & 31;
    const int wid  = tid >> 5;
    const int wm   = wid >> 2;
    const int wn   = wid & 3;
    const int row0 = blockIdx.x * 128;
    const int h    = blockIdx.y;

    float* asp = reinterpret_cast<float*>(smem + GG_ASP);
    __half* bsp = reinterpret_cast<__half*>(smem + GG_BSP);

    if (tid == 0) mbar_init(sb, 1);
    __syncthreads();

    if (tid == 0) {
        mbar_expect_tx(sb, (uint32_t)(3 * GG_MAT));
        #pragma unroll
        for (int c = 0; c < 4; c++) {
            int kx = c * 32;
            tma2d(tiles + 0 * GG_MAT + c * GG_CH, &mXh,  h * HD + kx, row0,   sb);
            tma2d(tiles + 1 * GG_MAT + c * GG_CH, &mWaH, kx,          h * HD, sb);
            tma2d(tiles + 2 * GG_MAT + c * GG_CH, &mWiH, kx,          h * HD, sb);
        }
    }
    mbar_wait(sb, 0);
    __syncthreads();

    uint32_t arow[4], axm[4], brow[2], bxm[2];
    #pragma unroll
    for (int im = 0; im < 4; im++) {
        int r = wm * 64 + im * 16 + (lane & 15);
        arow[im] = (uint32_t)(r * 64);
        axm[im]  = (uint32_t)((r & 6) << 3);
    }
    #pragma unroll
    for (int ip = 0; ip < 2; ip++) {
        int r = wn * 32 + ip * 16 + (lane & 7) + ((lane >> 4) & 1) * 8;
        brow[ip] = (uint32_t)(r * 64);
        bxm[ip]  = (uint32_t)((r & 6) << 3);
    }
    const uint32_t acol = (uint32_t)((lane >> 4) * 16);
    const uint32_t bcol = (uint32_t)(((lane >> 3) & 1) * 16);

    float accR[4][4][4], accI[4][4][4];
    #pragma unroll
    for (int im = 0; im < 4; im++)
        #pragma unroll
        for (int in = 0; in < 4; in++)
            #pragma unroll
            for (int q = 0; q < 4; q++) { accR[im][in][q] = 0.0f; accI[im][in][q] = 0.0f; }

    #pragma unroll
    for (int c = 0; c < 4; c++) {
        const uint32_t sAh = tiles + 0 * GG_MAT + c * GG_CH;
        const uint32_t sWa = tiles + 1 * GG_MAT + c * GG_CH;
        const uint32_t sWi = tiles + 2 * GG_MAT + c * GG_CH;
        #pragma unroll
        for (int kk = 0; kk < 2; kk++) {
            uint32_t af[4][4], wa[4][2], wi[4][2];
            #pragma unroll
            for (int im = 0; im < 4; im++) {
                uint32_t rest = (acol + (uint32_t)(kk * 32)) ^ axm[im];
                ldmx4(af[im], sAh + arow[im] + rest);
            }
            #pragma unroll
            for (int ip = 0; ip < 2; ip++) {
                uint32_t rest = (bcol + (uint32_t)(kk * 32)) ^ bxm[ip];
                uint32_t r4[4];
                ldmx4(r4, sWa + brow[ip] + rest);
                wa[2*ip][0]=r4[0]; wa[2*ip][1]=r4[1]; wa[2*ip+1][0]=r4[2]; wa[2*ip+1][1]=r4[3];
                ldmx4(r4, sWi + brow[ip] + rest);
                wi[2*ip][0]=r4[0]; wi[2*ip][1]=r4[1]; wi[2*ip+1][0]=r4[2]; wi[2*ip+1][1]=r4[3];
            }
            #pragma unroll
            for (int im = 0; im < 4; im++)
                #pragma unroll
                for (int in = 0; in < 4; in++) {
                    mma16816(accR[im][in], af[im], wa[in]);
                    mma16816(accI[im][in], af[im], wi[in]);
                }
        }
    }
    __syncthreads();

    const int gid = lane >> 2, t4 = lane & 3;
    #pragma unroll
    for (int in = 0; in < 4; in++) {
        int c0 = wn * 32 + in * 8 + t4 * 2;
        #pragma unroll
        for (int q = 0; q < 2; q++) {
            int col = c0 + q;
            int dd  = h * HD + col;
            float ab_ = ab[dd], ib_ = ib[dd];
            float sp  = log1pf(expf(-apar[dd]));
            int cch = col >> 5;
            uint32_t cb = (uint32_t)((col & 31) * 2);
            uint32_t cbase = (uint32_t)(cch * GG_CH);
            #pragma unroll
            for (int im = 0; im < 4; im++) {
                #pragma unroll
                for (int half = 0; half < 2; half++) {
                    int row = wm * 64 + im * 16 + gid + half * 8;
                    float rv = accR[im][in][half * 2 + q] + ab_;
                    float iv = accI[im][in][half * 2 + q] + ib_;
                    float r  = 1.0f / (1.0f + expf(-rv));
                    float ii = 1.0f / (1.0f + expf(-iv));
                    float la = -8.0f * r * sp;
                    float a  = expf(la);
                    __half omh = __float2half_rn(1.0f - a);
                    float aq = 1.0f - __half2float(omh);
                    float mult = sqrtf(fmaxf(1.0f - expf(2.0f * la), 0.0f));
                    uint32_t off = cbase + (uint32_t)(row * 64)
                                 + ((cb & 48u) ^ (uint32_t)((row & 6) << 3)) + (cb & 15u);
                    float xcv = __half2float(*reinterpret_cast<const __half*>(
                                    smem + GG_HDR + off));
                    __half bh = __float2half_rn(mult * ii * xcv);
                    size_t g = (size_t)(row0 + row) * D + dd;
                    omah[g] = omh;
                    gbh[g]  = bh;
                    int sidx = row * 128 + (col ^ (row & 31));
                    asp[sidx] = aq;
                    bsp[sidx] = bh;
                }
            }
        }
    }
    __syncthreads();

    if (tid < 128) {
        int col = tid;
        float hh = 0.0f, A = 1.0f;
        #pragma unroll 4
        for (int row = 0; row < 128; row++) {
            int sidx = row * 128 + (col ^ (row & 31));
            float a = asp[sidx];
            hh = fmaf(a, hh, __half2float(bsp[sidx]));
            A *= a;
        }
        int bb = row0 / S;
        int cc = (row0 % S) / SC_L;
        size_t o = ((size_t)bb * SC_NC + cc) * D + (size_t)h * HD + col;
        hend[o] = hh;
        aend[o] = A;
    }
}

// =====================================================================
// combined weight transpose/convert
// =====================================================================
__global__ void __launch_bounds__(256)
trans_all(const float* __restrict__ W0, __half* __restrict__ T0,
          const float* __restrict__ W1, __half* __restrict__ T1,
          const float* __restrict__ W2, __half* __restrict__ T2,
          const float* __restrict__ W3, __half* __restrict__ T3,
          const float* __restrict__ W4, __half* __restrict__ T4,
          const float* __restrict__ W5, __half* __restrict__ T5)
{
    using namespace hk;
    __shared__ float t[64][65];
    int b = blockIdx.x;
    const float* W; __half* Wt; int K, N, lb;
    if      (b < 1024)  { W = W0; Wt = T0; K = D; N = D; lb = b; }
    else if (b < 2048)  { W = W1; Wt = T1; K = D; N = D; lb = b - 1024; }
    else if (b < 3072)  { W = W2; Wt = T2; K = D; N = D; lb = b - 2048; }
    else if (b < 7168)  { W = W3; Wt = T3; K = D; N = F; lb = b - 3072; }
    else if (b < 11264) { W = W4; Wt = T4; K = D; N = F; lb = b - 7168; }
    else                { W = W5; Wt = T5; K = F; N = D; lb = b - 11264; }
    int nbx = N >> 6;
    int n0 = (lb % nbx) * 64, k0 = (lb / nbx) * 64;

    int tid = threadIdx.x;
    int lr = tid >> 4;
    int lc = (tid & 15) * 4;
    #pragma unroll
    for (int i = 0; i < 4; i++) {
        int r = lr + i * 16;
        float4 v = *reinterpret_cast<const float4*>(&W[(size_t)(k0 + r) * N + n0 + lc]);
        t[r][lc] = v.x; t[r][lc + 1] = v.y; t[r][lc + 2] = v.z; t[r][lc + 3] = v.w;
    }
    __syncthreads();
    #pragma unroll
    for (int i = 0; i < 2; i++) {
        int task = tid + i * 256;
        int n  = task >> 3;
        int kg = (task & 7) * 8;
        __half h8[8];
        #pragma unroll
        for (int j = 0; j < 8; j++) h8[j] = __float2half_rn(t[kg + j][n]);
        *reinterpret_cast<uint4*>(&Wt[(size_t)(n0 + n) * K + k0 + kg]) =
            *reinterpret_cast<uint4*>(h8);
    }
}

// gate-weight transpose: both weights in one launch (z in [0, 2H))
__global__ void trans_gate2(const float* __restrict__ Wa, __half* __restrict__ Ta,
                            const float* __restrict__ Wi, __half* __restrict__ Ti)
{
    using namespace hk;
    __shared__ float t[32][33];
    int e0 = blockIdx.x * 32, d0 = blockIdx.y * 32;
    int z = blockIdx.z;
    int hh = z & (H - 1);
    const float* W = (z < H) ? Wa : Wi;
    __half* T = (z < H) ? Ta : Ti;
    int tx = threadIdx.x, ty = threadIdx.y;
    const float* Wh = W + (size_t)hh * HD * HD;
    #pragma unroll
    for (int i = 0; i < 32; i += 8)
        t[ty + i][tx] = Wh[(size_t)(d0 + ty + i) * HD + (e0 + tx)];
    __syncthreads();
    #pragma unroll
    for (int i = 0; i < 32; i += 8) {
        size_t o = ((size_t)hh * HD + (e0 + ty + i)) * HD + (d0 + tx);
        T[o] = __float2half_rn(t[tx][ty + i]);
    }
}

// ---------------- vectorized rmsnorm ----------------
__global__ void __launch_bounds__(256)
rmsnorm_v(const float* __restrict__ x, const float* __restrict__ w,
          __half* __restrict__ o)
{
    using namespace hk;
    const int row = blockIdx.x;
    const int tid = threadIdx.x;
    const float4* xr = reinterpret_cast<const float4*>(x + (size_t)row * D);
    float4 v0 = xr[tid * 2];
    float4 v1 = xr[tid * 2 + 1];
    float ss = v0.x*v0.x + v0.y*v0.y + v0.z*v0.z + v0.w*v0.w
             + v1.x*v1.x + v1.y*v1.y + v1.z*v1.z + v1.w*v1.w;
    __shared__ float red[8];
    #pragma unroll
    for (int off = 16; off > 0; off >>= 1) ss += __shfl_down_sync(0xffffffffu, ss, off);
    if ((tid & 31) == 0) red[tid >> 5] = ss;
    __syncthreads();
    if (tid < 8) {
        float v = red[tid];
        #pragma unroll
        for (int off = 4; off > 0; off >>= 1) v += __shfl_down_sync(0xffu, v, off);
        if (tid == 0) red[0] = v;
    }
    __syncthreads();
    const float scale = rsqrtf(red[0] / (float)D + 1e-6f);
    const float4* wr = reinterpret_cast<const float4*>(w);
    float4 w0 = wr[tid * 2];
    float4 w1 = wr[tid * 2 + 1];
    __half h8[8];
    h8[0] = __float2half_rn(v0.x * scale * w0.x);
    h8[1] = __float2half_rn(v0.y * scale * w0.y);
    h8[2] = __float2half_rn(v0.z * scale * w0.z);
    h8[3] = __float2half_rn(v0.w * scale * w0.w);
    h8[4] = __float2half_rn(v1.x * scale * w1.x);
    h8[5] = __float2half_rn(v1.y * scale * w1.y);
    h8[6] = __float2half_rn(v1.z * scale * w1.z);
    h8[7] = __float2half_rn(v1.w * scale * w1.w);
    *reinterpret_cast<uint4*>(o + (size_t)row * D + tid * 8) =
        *reinterpret_cast<uint4*>(h8);
}

// ---------------- vectorized causal conv ----------------
__global__ void __launch_bounds__(256)
conv_v(const __half* __restrict__ xbh, const float* __restrict__ cw,
       const float* __restrict__ cb, __half* __restrict__ xcH)
{
    using namespace hk;
    size_t t = (size_t)blockIdx.x * blockDim.x + threadIdx.x;
    size_t base = t * 8;
    if (base >= NBSD) return;
    int d = (int)(base % D);
    int s = (int)((base / D) % S);
    float acc[8];
    {
        float4 c0 = *reinterpret_cast<const float4*>(cb + d);
        float4 c1 = *reinterpret_cast<const float4*>(cb + d + 4);
        acc[0]=c0.x; acc[1]=c0.y; acc[2]=c0.z; acc[3]=c0.w;
        acc[4]=c1.x; acc[5]=c1.y; acc[6]=c1.z; acc[7]=c1.w;
    }
    #pragma unroll
    for (int k = 0; k < 4; k++) {
        int ss = s + k - 3;
        if (ss >= 0) {
            uint4 xv = *reinterpret_cast<const uint4*>(xbh + base + (ptrdiff_t)(k - 3) * D);
            const __half2* xp = reinterpret_cast<const __half2*>(&xv);
            float4 w0 = *reinterpret_cast<const float4*>(cw + k * D + d);
            float4 w1 = *reinterpret_cast<const float4*>(cw + k * D + d + 4);
            float2 p0 = __half22float2(xp[0]);
            float2 p1 = __half22float2(xp[1]);
            float2 p2 = __half22float2(xp[2]);
            float2 p3 = __half22float2(xp[3]);
            acc[0] = fmaf(w0.x, p0.x, acc[0]);
            acc[1] = fmaf(w0.y, p0.y, acc[1]);
            acc[2] = fmaf(w0.z, p1.x, acc[2]);
            acc[3] = fmaf(w0.w, p1.y, acc[3]);
            acc[4] = fmaf(w1.x, p2.x, acc[4]);
            acc[5] = fmaf(w1.y, p2.y, acc[5]);
            acc[6] = fmaf(w1.z, p3.x, acc[6]);
            acc[7] = fmaf(w1.w, p3.y, acc[7]);
        }
    }
    __half h8[8];
    #pragma unroll
    for (int j = 0; j < 8; j++) h8[j] = __float2half_rn(acc[j]);
    *reinterpret_cast<uint4*>(xcH + base) = *reinterpret_cast<uint4*>(h8);
}

// ---------------- scan pass2 ----------------
__global__ void scan_pass2(const float* __restrict__ hend, const float* __restrict__ aend,
                           const float* __restrict__ h0, float* __restrict__ carry,
                           float* __restrict__ hlast)
{
    using namespace hk;
    int ch = blockIdx.x * blockDim.x + threadIdx.x;
    if (ch >= B * D) return;
    int b = ch / D, d = ch % D;
    float cur = h0[ch];
    for (int c = 0; c < SC_NC; c++) {
        size_t o = ((size_t)b * SC_NC + c) * D + d;
        carry[o] = cur;
        cur = fmaf(aend[o], cur, hend[o]);
    }
    if (hlast) hlast[ch] = cur;
}

// ---------------- scan pass3 ----------------
__global__ void scan_pass3(const __half* __restrict__ omah, const __half* __restrict__ gbh,
                           const float* __restrict__ carry, const __half* __restrict__ yA,
                           __half* __restrict__ zA)
{
    using namespace hk;
    int t = blockIdx.x * blockDim.x + threadIdx.x;
    if (t >= B * SC_NC * D) return;
    int d = t % D;
    int c = (t / D) % SC_NC;
    int b = t / (D * SC_NC);
    float h = carry[((size_t)b * SC_NC + c) * D + d];
    size_t g = ((size_t)b * S + (size_t)c * SC_L) * D + d;
    for (int i = 0; i < SC_L; i++, g += D) {
        float a = 1.0f - __half2float(omah[g]);
        h = fmaf(a, h, __half2float(gbh[g]));
        zA[g] = __float2half_rn(__half2float(yA[g]) * h);
    }
}

// =====================================================================
// host-side tensormap encoding (driver symbol via dlsym)
// =====================================================================
typedef CUresult (*EncodeFn)(CUtensorMap*, CUtensorMapDataType, cuuint32_t, void*,
                             const cuuint64_t*, const cuuint64_t*, const cuuint32_t*,
                             const cuuint32_t*, CUtensorMapInterleave, CUtensorMapSwizzle,
                             CUtensorMapL2promotion, CUtensorMapFloatOOBfill);

static EncodeFn get_encode() {
    static EncodeFn fn = nullptr;
    if (!fn) {
        fn = (EncodeFn)dlsym(RTLD_DEFAULT, "cuTensorMapEncodeTiled");
        if (!fn) {
            void* h = dlopen("libcuda.so.1", RTLD_LAZY | RTLD_GLOBAL);
            if (h) fn = (EncodeFn)dlsym(h, "cuTensorMapEncodeTiled");
        }
    }
    return fn;
}

static void enc_map(CUtensorMap* m, void* ptr, uint64_t K, uint64_t ROWS, uint32_t boxRows) {
    cuuint64_t dims[2]    = {K, ROWS};
    cuuint64_t strides[1] = {K * 2};
    cuuint32_t box[2]     = {32, boxRows};
    cuuint32_t es[2]      = {1, 1};
    get_encode()(m, CU_TENSOR_MAP_DATA_TYPE_FLOAT16, 2, ptr, dims, strides, box, es,
                 CU_TENSOR_MAP_INTERLEAVE_NONE, CU_TENSOR_MAP_SWIZZLE_64B,
                 CU_TENSOR_MAP_L2_PROMOTION_L2_128B, CU_TENSOR_MAP_FLOAT_OOB_FILL_NONE);
}

// ---------------- launch ----------------
extern "C" void kernel_launch(void* const* d_in, const int* in_sizes, int n_in,
                              void* d_out, int out_size)
{
    using namespace hk;
    const float* x    = (const float*)d_in[0];
    const float* h0   = (const float*)d_in[1];
    const float* r1w  = (const float*)d_in[2];
    const float* r2w  = (const float*)d_in[3];
    const float* Wx   = (const float*)d_in[4];
    const float* Wy   = (const float*)d_in[5];
    const float* cw   = (const float*)d_in[6];
    const float* cb   = (const float*)d_in[7];
    const float* apar = (const float*)d_in[8];
    const float* igw  = (const float*)d_in[9];
    const float* igb  = (const float*)d_in[10];
    const float* agw  = (const float*)d_in[11];
    const float* agb  = (const float*)d_in[12];
    const float* Wout = (const float*)d_in[13];
    const float* Wg   = (const float*)d_in[14];
    const float* Wu   = (const float*)d_in[15];
    const float* Wd   = (const float*)d_in[16];
    float* out = (float*)d_out;

    float *resid, *hend, *aend, *carry;
    cudaGetSymbolAddress((void**)&resid, g_resid);
    cudaGetSymbolAddress((void**)&hend,  g_hend);
    cudaGetSymbolAddress((void**)&aend,  g_aend);
    cudaGetSymbolAddress((void**)&carry, g_carry);

    __half *omah,*gbh,*nA,*yA,*xbh,*xcH,*zA,*n2A,*GA,*guA;
    __half *tWyx,*tWo,*tWg,*tWu,*tWd,*aWH,*iWH;
    cudaGetSymbolAddress((void**)&omah, g_omah);
    cudaGetSymbolAddress((void**)&gbh, g_gbh);
    cudaGetSymbolAddress((void**)&nA,  g_nA);
    cudaGetSymbolAddress((void**)&yA,  g_yA);
    cudaGetSymbolAddress((void**)&xbh, g_xbh);
    cudaGetSymbolAddress((void**)&xcH, g_xcH);
    cudaGetSymbolAddress((void**)&zA,  g_zA);
    cudaGetSymbolAddress((void**)&n2A, g_n2A);
    cudaGetSymbolAddress((void**)&GA,  g_GA);
    cudaGetSymbolAddress((void**)&guA, g_guA);
    cudaGetSymbolAddress((void**)&tWyx, g_Wyx);
    cudaGetSymbolAddress((void**)&tWo, g_Wo);  cudaGetSymbolAddress((void**)&tWg, g_Wg);
    cudaGetSymbolAddress((void**)&tWu, g_Wu);  cudaGetSymbolAddress((void**)&tWd, g_Wd);
    cudaGetSymbolAddress((void**)&aWH, g_aWH); cudaGetSymbolAddress((void**)&iWH, g_iWH);

    // ---- tensormaps ----
    static CUtensorMap mnA, mzA, mn2A, mguA;
    static CUtensorMap mWyx, mWo, mWg, mWu, mWd;
    static CUtensorMap mXh, mWaH, mWiH;
    enc_map(&mnA,  nA,  D, BS, 128);
    enc_map(&mzA,  zA,  D, BS, 128);
    enc_map(&mn2A, n2A, D, BS, 128);
    enc_map(&mguA, guA, F, BS, 128);
    enc_map(&mWyx, tWyx, D, 2 * (uint64_t)D, 256);
    enc_map(&mWo,  tWo, D, D, 256);   enc_map(&mWg,  tWg, D, F, 256);
    enc_map(&mWu,  tWu, D, F, 256);   enc_map(&mWd,  tWd, F, D, 256);
    enc_map(&mXh,  xcH, D, BS, 128);
    enc_map(&mWaH, aWH, HD, (uint64_t)H * HD, 128);
    enc_map(&mWiH, iWH, HD, (uint64_t)H * HD, 128);

    cudaFuncSetAttribute(gemm_tma<2>, cudaFuncAttributeMaxDynamicSharedMemorySize, GT_SMEM);
    cudaFuncSetAttribute(gemm_tma<3>, cudaFuncAttributeMaxDynamicSharedMemorySize, GT_SMEM);
    cudaFuncSetAttribute(gemm_tma<4>, cudaFuncAttributeMaxDynamicSharedMemorySize, GT_SMEM);
    cudaFuncSetAttribute(gemm_dual,   cudaFuncAttributeMaxDynamicSharedMemorySize, GT_SMEM);
    cudaFuncSetAttribute(gate_mma,    cudaFuncAttributeMaxDynamicSharedMemorySize, GG_SMEM);

    float* hlast = (out_size >= (int)(NBSD + (size_t)B * D)) ? (out + NBSD) : nullptr;

    // ---- weight transpose/convert ----
    trans_all<<<15360, 256>>>(Wy, tWyx, Wx, tWyx + NDD, Wout, tWo,
                              Wg, tWg, Wu, tWu, Wd, tWd);
    trans_gate2<<<dim3(HD / 32, HD / 32, 2 * H), dim3(32, 8)>>>(agw, aWH, igw, iWH);

    // ---- temporal pre-norm (vectorized) ----
    rmsnorm_v<<<BS, 256>>>(x, r1w, nA);

    // ---- combined: y = gelu(nA @ Wy) fp16 AND xb = nA @ Wx fp16 ----
    dim3 gDual(2 * D / 256, BS / 128);
    gemm_dual<<<gDual, GT_THR, GT_SMEM>>>(mnA, mWyx, yA, xbh, D, D);

    // ---- causal conv (vectorized) ----
    conv_v<<<(unsigned)(NBSD / 8 / 256), 256>>>(xbh, cw, cb, xcH);

    // ---- fused gate GEMM + gate math + chunk-end scan ----
    gate_mma<<<dim3(BS / 128, H), 256, GG_SMEM>>>(mXh, mWaH, mWiH,
                                                  agb, igb, apar, omah, gbh, hend, aend);

    // ---- carries + final rescan fused with y-mul ----
    scan_pass2<<<(B * D + 255) / 256, 256>>>(hend, aend, h0, carry, hlast);
    scan_pass3<<<(B * SC_NC * D + 255) / 256, 256>>>(omah, gbh, carry, yA, zA);

    // ---- residual = z @ W_out + x ----
    dim3 gDD(D / 256, BS / 128);
    gemm_tma<2><<<gDD, GT_THR, GT_SMEM>>>(mzA, mWo, resid, x, nullptr, nullptr, D, D);

    // ---- second norm (vectorized) ----
    rmsnorm_v<<<BS, 256>>>(resid, r2w, n2A);

    // ---- MLP: G = gelu(n2 @ Wg) fp16; gu = (n2 @ Wu) * G fp16 ----
    dim3 gDF(F / 256, BS / 128);
    gemm_tma<4><<<gDF, GT_THR, GT_SMEM>>>(mn2A, mWg, nullptr, nullptr, nullptr, GA, F, D);
    gemm_tma<3><<<gDF, GT_THR, GT_SMEM>>>(mn2A, mWu, nullptr, nullptr, GA, guA, F, D);

    // ---- out = gu @ W_down + residual ----
    gemm_tma<2><<<gDD, GT_THR, GT_SMEM>>>(mguA, mWd, out, resid, nullptr, nullptr, D, F);
}

// round 16
// speedup vs baseline: 1.0664x; 1.0664x over previous
#include <cuda_runtime.h>
#include <cuda.h>
#include <cuda_fp16.h>
#include <math.h>
#include <stdint.h>
#include <dlfcn.h>

// ---------------- problem constants ----------------
namespace hk {
constexpr int B  = 2;
constexpr int S  = 2048;
constexpr int D  = 2048;
constexpr int H  = 16;
constexpr int HD = 128;
constexpr int F  = 8192;
constexpr int BS = B * S;                     // 4096 rows
constexpr size_t NBSD = (size_t)BS * D;       // 8,388,608
constexpr size_t NBSF = (size_t)BS * F;       // 33,554,432
constexpr size_t NDD  = (size_t)D * D;
constexpr size_t NDF  = (size_t)D * F;
constexpr size_t NGW  = (size_t)H * HD * HD;  // 262,144
}

constexpr int SC_NC = 16;                      // scan chunks
constexpr int SC_L  = hk::S / SC_NC;           // 128 steps per chunk

// ---------------- scratch: fp32 intermediates ----------------
__device__ float g_resid [hk::NBSD];
__device__ float g_hend  [hk::B * hk::D * SC_NC];
__device__ float g_aend  [hk::B * hk::D * SC_NC];
__device__ float g_carry [hk::B * hk::D * SC_NC];

// ---------------- scratch: fp16 activations ----------------
__device__ __half g_omah[hk::NBSD];            // 1 - a
__device__ __half g_gbh [hk::NBSD];            // b
__device__ __half g_nA  [hk::NBSD];
__device__ __half g_yA  [hk::NBSD];
__device__ __half g_xbh [hk::NBSD];
__device__ __half g_xcH [hk::NBSD];
__device__ __half g_zA  [hk::NBSD];
__device__ __half g_n2A [hk::NBSD];
__device__ __half g_GA  [hk::NBSF];
__device__ __half g_guA [hk::NBSF];

// ---------------- scratch: fp16 transposed weights [N,K] ----------------
__device__ __half g_Wyx[2 * hk::NDD];          // [Wy ; Wx] concatenated on N
__device__ __half g_Wo[hk::NDD];
__device__ __half g_Wg[hk::NDF];
__device__ __half g_Wu[hk::NDF];
__device__ __half g_Wd[hk::NDF];
// gate weights, transposed per head [H][e][d], single fp16
__device__ __half g_aWH[hk::NGW];
__device__ __half g_iWH[hk::NGW];

// ---------------- helpers ----------------
__device__ __forceinline__ float gelu_tanh(float x) {
    float x3 = x * x * x;
    return 0.5f * x * (1.0f + tanhf(0.7978845608028654f * (x + 0.044715f * x3)));
}

__device__ __forceinline__ uint32_t s2u(const void* p) {
    uint32_t a;
    asm("{ .reg .u64 t; cvta.to.shared.u64 t, %1; cvt.u32.u64 %0, t; }" : "=r"(a) : "l"(p));
    return a;
}

__device__ __forceinline__ void ldmx4(uint32_t* r, uint32_t a) {
    asm volatile("ldmatrix.sync.aligned.m8n8.x4.shared.b16 {%0,%1,%2,%3}, [%4];"
                 : "=r"(r[0]), "=r"(r[1]), "=r"(r[2]), "=r"(r[3]) : "r"(a));
}

__device__ __forceinline__ void mma16816(float* c, const uint32_t* a, const uint32_t* b) {
    asm volatile(
        "mma.sync.aligned.m16n8k16.row.col.f32.f16.f16.f32 "
        "{%0,%1,%2,%3}, {%4,%5,%6,%7}, {%8,%9}, {%0,%1,%2,%3};"
        : "+f"(c[0]), "+f"(c[1]), "+f"(c[2]), "+f"(c[3])
        : "r"(a[0]), "r"(a[1]), "r"(a[2]), "r"(a[3]), "r"(b[0]), "r"(b[1]));
}

__device__ __forceinline__ void mbar_init(uint32_t mbar, uint32_t cnt) {
    asm volatile("mbarrier.init.shared.b64 [%0], %1;" :: "r"(mbar), "r"(cnt) : "memory");
}

__device__ __forceinline__ void mbar_expect_tx(uint32_t mbar, uint32_t bytes) {
    asm volatile("mbarrier.arrive.expect_tx.shared.b64 _, [%0], %1;"
                 :: "r"(mbar), "r"(bytes) : "memory");
}

__device__ __forceinline__ void mbar_wait(uint32_t mbar, uint32_t phase) {
    asm volatile(
        "{\n\t.reg .pred P;\n\t"
        "WAIT_%=:\n\t"
        "mbarrier.try_wait.parity.shared.b64 P, [%0], %1, 10000000;\n\t"
        "@P bra.uni DONE_%=;\n\t"
        "bra.uni WAIT_%=;\n\t"
        "DONE_%=:\n\t}"
        :: "r"(mbar), "r"(phase) : "memory");
}

__device__ __forceinline__ void tma2d(uint32_t dst, const CUtensorMap* map,
                                      int cx, int cy, uint32_t mbar) {
    asm volatile(
        "cp.async.bulk.tensor.2d.shared::cluster.global.tile.mbarrier::complete_tx::bytes "
        "[%0], [%1, {%2, %3}], [%4];"
        :: "r"(dst), "l"(map), "r"(cx), "r"(cy), "r"(mbar) : "memory");
}

// =====================================================================
// GEMM core: 256 threads (8 warps 2x4, 64x64 warp tile), CTA tile
// 128x256, TMA loads (SW64), EIGHT-stage mbarrier pipeline, FOUR
// K-blocks per __syncthreads (the round-14 winning cadence; one extra
// stage of prefetch slack, power-of-two slot math).
// =====================================================================
constexpr int GT_NSTG  = 8;
constexpr int GT_TA    = 128 * 64;              // 8192 B A tile
constexpr int GT_TB    = 256 * 64;              // 16384 B B tile
constexpr int GT_STAGE = GT_TA + GT_TB;         // 24576 B
constexpr int GT_HDR   = 1024;
constexpr int GT_SMEM  = GT_HDR + GT_NSTG * GT_STAGE;   // 197632 B
constexpr int GT_THR   = 256;

#define GEMM_MAINLOOP(mA_, mB_)                                                   \
    const uint32_t sb    = s2u(smem);                                             \
    const uint32_t tiles = sb + GT_HDR;                                           \
    const int tid  = threadIdx.x;                                                 \
    const int lane = tid & 31;                                                    \
    const int wid  = tid >> 5;                                                    \
    const int wm   = wid >> 2;        /* 0..1 -> 64-row slab */                   \
    const int wn   = wid & 3;         /* 0..3 -> 64-col slab */                   \
    const int row0 = blockIdx.y * 128;                                            \
    const int col0 = blockIdx.x * 256;                                            \
    const int KB   = K >> 5;                                                      \
    if (tid == 0) {                                                               \
        _Pragma("unroll")                                                         \
        for (int s = 0; s < GT_NSTG; s++) mbar_init(sb + s * 8, 1);               \
    }                                                                             \
    __syncthreads();                                                              \
    uint32_t arow[4], axm[4], brow[4], bxm[4];                                    \
    _Pragma("unroll")                                                             \
    for (int im = 0; im < 4; im++) {                                              \
        int r = wm * 64 + im * 16 + (lane & 15);                                  \
        arow[im] = (uint32_t)(r * 64);                                            \
        axm[im]  = (uint32_t)((r & 6) << 3);                                      \
    }                                                                             \
    _Pragma("unroll")                                                             \
    for (int ip = 0; ip < 4; ip++) {                                              \
        int r = wn * 64 + ip * 16 + (lane & 7) + ((lane >> 4) & 1) * 8;           \
        brow[ip] = (uint32_t)(r * 64);                                            \
        bxm[ip]  = (uint32_t)((r & 6) << 3);                                      \
    }                                                                             \
    const uint32_t acol = (uint32_t)((lane >> 4) * 16);                           \
    const uint32_t bcol = (uint32_t)(((lane >> 3) & 1) * 16);                     \
    float acc[4][8][4];                                                           \
    _Pragma("unroll")                                                             \
    for (int im = 0; im < 4; im++)                                                \
        _Pragma("unroll")                                                         \
        for (int in = 0; in < 8; in++)                                            \
            _Pragma("unroll")                                                     \
            for (int q = 0; q < 4; q++) acc[im][in][q] = 0.0f;                    \
    auto issue = [&](int kb) {                                                    \
        int slot = kb & (GT_NSTG - 1);                                            \
        uint32_t bar = sb + slot * 8;                                             \
        uint32_t st  = tiles + (uint32_t)slot * GT_STAGE;                         \
        mbar_expect_tx(bar, (uint32_t)GT_STAGE);                                  \
        tma2d(st,         &mA_, kb * 32, row0, bar);                              \
        tma2d(st + GT_TA, &mB_, kb * 32, col0, bar);                              \
    };                                                                            \
    auto compute = [&](int kb) {                                                  \
        const uint32_t sA = tiles + (uint32_t)(kb & (GT_NSTG - 1)) * GT_STAGE;    \
        const uint32_t sB = sA + GT_TA;                                           \
        _Pragma("unroll")                                                         \
        for (int kk = 0; kk < 2; kk++) {                                          \
            uint32_t af[4][4], bf[8][2];                                          \
            _Pragma("unroll")                                                     \
            for (int im = 0; im < 4; im++) {                                      \
                uint32_t rest = (acol + (uint32_t)(kk * 32)) ^ axm[im];           \
                ldmx4(af[im], sA + arow[im] + rest);                              \
            }                                                                     \
            _Pragma("unroll")                                                     \
            for (int ip = 0; ip < 4; ip++) {                                      \
                uint32_t rest = (bcol + (uint32_t)(kk * 32)) ^ bxm[ip];           \
                uint32_t r4[4];                                                   \
                ldmx4(r4, sB + brow[ip] + rest);                                  \
                bf[2 * ip + 0][0] = r4[0]; bf[2 * ip + 0][1] = r4[1];             \
                bf[2 * ip + 1][0] = r4[2]; bf[2 * ip + 1][1] = r4[3];             \
            }                                                                     \
            _Pragma("unroll")                                                     \
            for (int im = 0; im < 4; im++)                                        \
                _Pragma("unroll")                                                 \
                for (int in = 0; in < 8; in++)                                    \
                    mma16816(acc[im][in], af[im], bf[in]);                        \
        }                                                                         \
    };                                                                            \
    if (tid == 0) {                                                               \
        _Pragma("unroll")                                                         \
        for (int s = 0; s < GT_NSTG - 1; s++) issue(s);                           \
    }                                                                             \
    for (int kb = 0; kb < KB; kb += 4) {                                          \
        _Pragma("unroll")                                                         \
        for (int j = 0; j < 4; j++) {                                             \
            mbar_wait(sb + (((kb + j) & (GT_NSTG - 1)) * 8),                      \
                      (uint32_t)(((kb + j) / GT_NSTG) & 1));                      \
            compute(kb + j);                                                      \
        }                                                                         \
        __syncthreads();                                                          \
        if (tid == 0) {                                                           \
            _Pragma("unroll")                                                     \
            for (int j = 0; j < 4; j++)                                           \
                if (kb + GT_NSTG - 1 + j < KB) issue(kb + GT_NSTG - 1 + j);       \
        }                                                                         \
    }

// =====================================================================
// gemm_tma: EPI 2 add aux fp32 -> C fp32; 3 mul auxh fp16 -> OH fp16;
//           4 gelu -> OH fp16.
// =====================================================================
template<int EPI>
__global__ void __launch_bounds__(GT_THR, 1)
gemm_tma(const __grid_constant__ CUtensorMap mA,
         const __grid_constant__ CUtensorMap mB,
         float* __restrict__ C, const float* __restrict__ aux,
         const __half* __restrict__ auxh, __half* __restrict__ OH,
         int N, int K)
{
    extern __shared__ __align__(1024) char smem[];
    GEMM_MAINLOOP(mA, mB)

    const int gid = lane >> 2, t4 = lane & 3;
    #pragma unroll
    for (int im = 0; im < 4; im++) {
        #pragma unroll
        for (int in = 0; in < 8; in++) {
            int r = row0 + wm * 64 + im * 16 + gid;
            int c = col0 + wn * 64 + in * 8 + t4 * 2;
            #pragma unroll
            for (int half = 0; half < 2; half++) {
                int rr = r + half * 8;
                float v0 = acc[im][in][half * 2 + 0];
                float v1 = acc[im][in][half * 2 + 1];
                if (EPI == 2) {
                    float2 a2 = *reinterpret_cast<const float2*>(aux + (size_t)rr * N + c);
                    v0 += a2.x; v1 += a2.y;
                    float2 o; o.x = v0; o.y = v1;
                    *reinterpret_cast<float2*>(C + (size_t)rr * N + c) = o;
                } else if (EPI == 3) {
                    __half2 a2 = *reinterpret_cast<const __half2*>(auxh + (size_t)rr * N + c);
                    v0 *= __half2float(a2.x); v1 *= __half2float(a2.y);
                    __half2 hp; hp.x = __float2half_rn(v0); hp.y = __float2half_rn(v1);
                    *reinterpret_cast<__half2*>(OH + (size_t)rr * N + c) = hp;
                } else {   // EPI == 4: gelu
                    v0 = gelu_tanh(v0); v1 = gelu_tanh(v1);
                    __half2 hp; hp.x = __float2half_rn(v0); hp.y = __float2half_rn(v1);
                    *reinterpret_cast<__half2*>(OH + (size_t)rr * N + c) = hp;
                }
            }
        }
    }
}

// =====================================================================
// gemm_dual: combined Wy+Wx GEMM over concatenated B [2*NOUT, K].
// =====================================================================
__global__ void __launch_bounds__(GT_THR, 1)
gemm_dual(const __grid_constant__ CUtensorMap mA,
          const __grid_constant__ CUtensorMap mB,
          __half* __restrict__ O1, __half* __restrict__ O2,
          int NOUT, int K)
{
    extern __shared__ __align__(1024) char smem[];
    GEMM_MAINLOOP(mA, mB)

    const bool side = (col0 >= NOUT);
    __half* dst = side ? O2 : O1;
    const int cb0 = side ? (col0 - NOUT) : col0;

    const int gid = lane >> 2, t4 = lane & 3;
    #pragma unroll
    for (int im = 0; im < 4; im++) {
        #pragma unroll
        for (int in = 0; in < 8; in++) {
            int r = row0 + wm * 64 + im * 16 + gid;
            int c = cb0 + wn * 64 + in * 8 + t4 * 2;
            #pragma unroll
            for (int half = 0; half < 2; half++) {
                int rr = r + half * 8;
                float v0 = acc[im][in][half * 2 + 0];
                float v1 = acc[im][in][half * 2 + 1];
                if (!side) { v0 = gelu_tanh(v0); v1 = gelu_tanh(v1); }
                __half2 hp; hp.x = __float2half_rn(v0); hp.y = __float2half_rn(v1);
                *reinterpret_cast<__half2*>(dst + (size_t)rr * NOUT + c) = hp;
            }
        }
    }
}

// =====================================================================
// gate_mma (unchanged winner)
// =====================================================================
constexpr int GG_CH   = 8192;
constexpr int GG_MAT  = 4 * GG_CH;
constexpr int GG_HDR  = 1024;
constexpr int GG_ASP  = GG_HDR + GG_MAT;
constexpr int GG_BSP  = GG_HDR + 3 * GG_MAT;
constexpr int GG_SMEM = GG_BSP + 32768;       // 132096 B

__global__ void __launch_bounds__(256, 1)
gate_mma(const __grid_constant__ CUtensorMap mXh,
         const __grid_constant__ CUtensorMap mWaH,
         const __grid_constant__ CUtensorMap mWiH,
         const float* __restrict__ ab, const float* __restrict__ ib,
         const float* __restrict__ apar,
         __half* __restrict__ omah, __half* __restrict__ gbh,
         float* __restrict__ hend, float* __restrict__ aend)
{
    using namespace hk;
    extern __shared__ __align__(1024) char smem[];
    const uint32_t sb    = s2u(smem);
    const uint32_t tiles = sb + GG_HDR;

    const int tid  = threadIdx.x;
    const int lane = tid & 31;
    const int wid  = tid >> 5;
    const int wm   = wid >> 2;
    const int wn   = wid & 3;
    const int row0 = blockIdx.x * 128;
    const int h    = blockIdx.y;

    float* asp = reinterpret_cast<float*>(smem + GG_ASP);
    __half* bsp = reinterpret_cast<__half*>(smem + GG_BSP);

    if (tid == 0) mbar_init(sb, 1);
    __syncthreads();

    if (tid == 0) {
        mbar_expect_tx(sb, (uint32_t)(3 * GG_MAT));
        #pragma unroll
        for (int c = 0; c < 4; c++) {
            int kx = c * 32;
            tma2d(tiles + 0 * GG_MAT + c * GG_CH, &mXh,  h * HD + kx, row0,   sb);
            tma2d(tiles + 1 * GG_MAT + c * GG_CH, &mWaH, kx,          h * HD, sb);
            tma2d(tiles + 2 * GG_MAT + c * GG_CH, &mWiH, kx,          h * HD, sb);
        }
    }
    mbar_wait(sb, 0);
    __syncthreads();

    uint32_t arow[4], axm[4], brow[2], bxm[2];
    #pragma unroll
    for (int im = 0; im < 4; im++) {
        int r = wm * 64 + im * 16 + (lane & 15);
        arow[im] = (uint32_t)(r * 64);
        axm[im]  = (uint32_t)((r & 6) << 3);
    }
    #pragma unroll
    for (int ip = 0; ip < 2; ip++) {
        int r = wn * 32 + ip * 16 + (lane & 7) + ((lane >> 4) & 1) * 8;
        brow[ip] = (uint32_t)(r * 64);
        bxm[ip]  = (uint32_t)((r & 6) << 3);
    }
    const uint32_t acol = (uint32_t)((lane >> 4) * 16);
    const uint32_t bcol = (uint32_t)(((lane >> 3) & 1) * 16);

    float accR[4][4][4], accI[4][4][4];
    #pragma unroll
    for (int im = 0; im < 4; im++)
        #pragma unroll
        for (int in = 0; in < 4; in++)
            #pragma unroll
            for (int q = 0; q < 4; q++) { accR[im][in][q] = 0.0f; accI[im][in][q] = 0.0f; }

    #pragma unroll
    for (int c = 0; c < 4; c++) {
        const uint32_t sAh = tiles + 0 * GG_MAT + c * GG_CH;
        const uint32_t sWa = tiles + 1 * GG_MAT + c * GG_CH;
        const uint32_t sWi = tiles + 2 * GG_MAT + c * GG_CH;
        #pragma unroll
        for (int kk = 0; kk < 2; kk++) {
            uint32_t af[4][4], wa[4][2], wi[4][2];
            #pragma unroll
            for (int im = 0; im < 4; im++) {
                uint32_t rest = (acol + (uint32_t)(kk * 32)) ^ axm[im];
                ldmx4(af[im], sAh + arow[im] + rest);
            }
            #pragma unroll
            for (int ip = 0; ip < 2; ip++) {
                uint32_t rest = (bcol + (uint32_t)(kk * 32)) ^ bxm[ip];
                uint32_t r4[4];
                ldmx4(r4, sWa + brow[ip] + rest);
                wa[2*ip][0]=r4[0]; wa[2*ip][1]=r4[1]; wa[2*ip+1][0]=r4[2]; wa[2*ip+1][1]=r4[3];
                ldmx4(r4, sWi + brow[ip] + rest);
                wi[2*ip][0]=r4[0]; wi[2*ip][1]=r4[1]; wi[2*ip+1][0]=r4[2]; wi[2*ip+1][1]=r4[3];
            }
            #pragma unroll
            for (int im = 0; im < 4; im++)
                #pragma unroll
                for (int in = 0; in < 4; in++) {
                    mma16816(accR[im][in], af[im], wa[in]);
                    mma16816(accI[im][in], af[im], wi[in]);
                }
        }
    }
    __syncthreads();

    const int gid = lane >> 2, t4 = lane & 3;
    #pragma unroll
    for (int in = 0; in < 4; in++) {
        int c0 = wn * 32 + in * 8 + t4 * 2;
        #pragma unroll
        for (int q = 0; q < 2; q++) {
            int col = c0 + q;
            int dd  = h * HD + col;
            float ab_ = ab[dd], ib_ = ib[dd];
            float sp  = log1pf(expf(-apar[dd]));
            int cch = col >> 5;
            uint32_t cb = (uint32_t)((col & 31) * 2);
            uint32_t cbase = (uint32_t)(cch * GG_CH);
            #pragma unroll
            for (int im = 0; im < 4; im++) {
                #pragma unroll
                for (int half = 0; half < 2; half++) {
                    int row = wm * 64 + im * 16 + gid + half * 8;
                    float rv = accR[im][in][half * 2 + q] + ab_;
                    float iv = accI[im][in][half * 2 + q] + ib_;
                    float r  = 1.0f / (1.0f + expf(-rv));
                    float ii = 1.0f / (1.0f + expf(-iv));
                    float la = -8.0f * r * sp;
                    float a  = expf(la);
                    __half omh = __float2half_rn(1.0f - a);
                    float aq = 1.0f - __half2float(omh);
                    float mult = sqrtf(fmaxf(1.0f - expf(2.0f * la), 0.0f));
                    uint32_t off = cbase + (uint32_t)(row * 64)
                                 + ((cb & 48u) ^ (uint32_t)((row & 6) << 3)) + (cb & 15u);
                    float xcv = __half2float(*reinterpret_cast<const __half*>(
                                    smem + GG_HDR + off));
                    __half bh = __float2half_rn(mult * ii * xcv);
                    size_t g = (size_t)(row0 + row) * D + dd;
                    omah[g] = omh;
                    gbh[g]  = bh;
                    int sidx = row * 128 + (col ^ (row & 31));
                    asp[sidx] = aq;
                    bsp[sidx] = bh;
                }
            }
        }
    }
    __syncthreads();

    if (tid < 128) {
        int col = tid;
        float hh = 0.0f, A = 1.0f;
        #pragma unroll 4
        for (int row = 0; row < 128; row++) {
            int sidx = row * 128 + (col ^ (row & 31));
            float a = asp[sidx];
            hh = fmaf(a, hh, __half2float(bsp[sidx]));
            A *= a;
        }
        int bb = row0 / S;
        int cc = (row0 % S) / SC_L;
        size_t o = ((size_t)bb * SC_NC + cc) * D + (size_t)h * HD + col;
        hend[o] = hh;
        aend[o] = A;
    }
}

// =====================================================================
// combined weight transpose/convert
// =====================================================================
__global__ void __launch_bounds__(256)
trans_all(const float* __restrict__ W0, __half* __restrict__ T0,
          const float* __restrict__ W1, __half* __restrict__ T1,
          const float* __restrict__ W2, __half* __restrict__ T2,
          const float* __restrict__ W3, __half* __restrict__ T3,
          const float* __restrict__ W4, __half* __restrict__ T4,
          const float* __restrict__ W5, __half* __restrict__ T5)
{
    using namespace hk;
    __shared__ float t[64][65];
    int b = blockIdx.x;
    const float* W; __half* Wt; int K, N, lb;
    if      (b < 1024)  { W = W0; Wt = T0; K = D; N = D; lb = b; }
    else if (b < 2048)  { W = W1; Wt = T1; K = D; N = D; lb = b - 1024; }
    else if (b < 3072)  { W = W2; Wt = T2; K = D; N = D; lb = b - 2048; }
    else if (b < 7168)  { W = W3; Wt = T3; K = D; N = F; lb = b - 3072; }
    else if (b < 11264) { W = W4; Wt = T4; K = D; N = F; lb = b - 7168; }
    else                { W = W5; Wt = T5; K = F; N = D; lb = b - 11264; }
    int nbx = N >> 6;
    int n0 = (lb % nbx) * 64, k0 = (lb / nbx) * 64;

    int tid = threadIdx.x;
    int lr = tid >> 4;
    int lc = (tid & 15) * 4;
    #pragma unroll
    for (int i = 0; i < 4; i++) {
        int r = lr + i * 16;
        float4 v = *reinterpret_cast<const float4*>(&W[(size_t)(k0 + r) * N + n0 + lc]);
        t[r][lc] = v.x; t[r][lc + 1] = v.y; t[r][lc + 2] = v.z; t[r][lc + 3] = v.w;
    }
    __syncthreads();
    #pragma unroll
    for (int i = 0; i < 2; i++) {
        int task = tid + i * 256;
        int n  = task >> 3;
        int kg = (task & 7) * 8;
        __half h8[8];
        #pragma unroll
        for (int j = 0; j < 8; j++) h8[j] = __float2half_rn(t[kg + j][n]);
        *reinterpret_cast<uint4*>(&Wt[(size_t)(n0 + n) * K + k0 + kg]) =
            *reinterpret_cast<uint4*>(h8);
    }
}

// gate-weight transpose: both weights in one launch (z in [0, 2H))
__global__ void trans_gate2(const float* __restrict__ Wa, __half* __restrict__ Ta,
                            const float* __restrict__ Wi, __half* __restrict__ Ti)
{
    using namespace hk;
    __shared__ float t[32][33];
    int e0 = blockIdx.x * 32, d0 = blockIdx.y * 32;
    int z = blockIdx.z;
    int hh = z & (H - 1);
    const float* W = (z < H) ? Wa : Wi;
    __half* T = (z < H) ? Ta : Ti;
    int tx = threadIdx.x, ty = threadIdx.y;
    const float* Wh = W + (size_t)hh * HD * HD;
    #pragma unroll
    for (int i = 0; i < 32; i += 8)
        t[ty + i][tx] = Wh[(size_t)(d0 + ty + i) * HD + (e0 + tx)];
    __syncthreads();
    #pragma unroll
    for (int i = 0; i < 32; i += 8) {
        size_t o = ((size_t)hh * HD + (e0 + ty + i)) * HD + (d0 + tx);
        T[o] = __float2half_rn(t[tx][ty + i]);
    }
}

// ---------------- vectorized rmsnorm ----------------
__global__ void __launch_bounds__(256)
rmsnorm_v(const float* __restrict__ x, const float* __restrict__ w,
          __half* __restrict__ o)
{
    using namespace hk;
    const int row = blockIdx.x;
    const int tid = threadIdx.x;
    const float4* xr = reinterpret_cast<const float4*>(x + (size_t)row * D);
    float4 v0 = xr[tid * 2];
    float4 v1 = xr[tid * 2 + 1];
    float ss = v0.x*v0.x + v0.y*v0.y + v0.z*v0.z + v0.w*v0.w
             + v1.x*v1.x + v1.y*v1.y + v1.z*v1.z + v1.w*v1.w;
    __shared__ float red[8];
    #pragma unroll
    for (int off = 16; off > 0; off >>= 1) ss += __shfl_down_sync(0xffffffffu, ss, off);
    if ((tid & 31) == 0) red[tid >> 5] = ss;
    __syncthreads();
    if (tid < 8) {
        float v = red[tid];
        #pragma unroll
        for (int off = 4; off > 0; off >>= 1) v += __shfl_down_sync(0xffu, v, off);
        if (tid == 0) red[0] = v;
    }
    __syncthreads();
    const float scale = rsqrtf(red[0] / (float)D + 1e-6f);
    const float4* wr = reinterpret_cast<const float4*>(w);
    float4 w0 = wr[tid * 2];
    float4 w1 = wr[tid * 2 + 1];
    __half h8[8];
    h8[0] = __float2half_rn(v0.x * scale * w0.x);
    h8[1] = __float2half_rn(v0.y * scale * w0.y);
    h8[2] = __float2half_rn(v0.z * scale * w0.z);
    h8[3] = __float2half_rn(v0.w * scale * w0.w);
    h8[4] = __float2half_rn(v1.x * scale * w1.x);
    h8[5] = __float2half_rn(v1.y * scale * w1.y);
    h8[6] = __float2half_rn(v1.z * scale * w1.z);
    h8[7] = __float2half_rn(v1.w * scale * w1.w);
    *reinterpret_cast<uint4*>(o + (size_t)row * D + tid * 8) =
        *reinterpret_cast<uint4*>(h8);
}

// ---------------- vectorized causal conv ----------------
__global__ void __launch_bounds__(256)
conv_v(const __half* __restrict__ xbh, const float* __restrict__ cw,
       const float* __restrict__ cb, __half* __restrict__ xcH)
{
    using namespace hk;
    size_t t = (size_t)blockIdx.x * blockDim.x + threadIdx.x;
    size_t base = t * 8;
    if (base >= NBSD) return;
    int d = (int)(base % D);
    int s = (int)((base / D) % S);
    float acc[8];
    {
        float4 c0 = *reinterpret_cast<const float4*>(cb + d);
        float4 c1 = *reinterpret_cast<const float4*>(cb + d + 4);
        acc[0]=c0.x; acc[1]=c0.y; acc[2]=c0.z; acc[3]=c0.w;
        acc[4]=c1.x; acc[5]=c1.y; acc[6]=c1.z; acc[7]=c1.w;
    }
    #pragma unroll
    for (int k = 0; k < 4; k++) {
        int ss = s + k - 3;
        if (ss >= 0) {
            uint4 xv = *reinterpret_cast<const uint4*>(xbh + base + (ptrdiff_t)(k - 3) * D);
            const __half2* xp = reinterpret_cast<const __half2*>(&xv);
            float4 w0 = *reinterpret_cast<const float4*>(cw + k * D + d);
            float4 w1 = *reinterpret_cast<const float4*>(cw + k * D + d + 4);
            float2 p0 = __half22float2(xp[0]);
            float2 p1 = __half22float2(xp[1]);
            float2 p2 = __half22float2(xp[2]);
            float2 p3 = __half22float2(xp[3]);
            acc[0] = fmaf(w0.x, p0.x, acc[0]);
            acc[1] = fmaf(w0.y, p0.y, acc[1]);
            acc[2] = fmaf(w0.z, p1.x, acc[2]);
            acc[3] = fmaf(w0.w, p1.y, acc[3]);
            acc[4] = fmaf(w1.x, p2.x, acc[4]);
            acc[5] = fmaf(w1.y, p2.y, acc[5]);
            acc[6] = fmaf(w1.z, p3.x, acc[6]);
            acc[7] = fmaf(w1.w, p3.y, acc[7]);
        }
    }
    __half h8[8];
    #pragma unroll
    for (int j = 0; j < 8; j++) h8[j] = __float2half_rn(acc[j]);
    *reinterpret_cast<uint4*>(xcH + base) = *reinterpret_cast<uint4*>(h8);
}

// ---------------- scan pass2 ----------------
__global__ void scan_pass2(const float* __restrict__ hend, const float* __restrict__ aend,
                           const float* __restrict__ h0, float* __restrict__ carry,
                           float* __restrict__ hlast)
{
    using namespace hk;
    int ch = blockIdx.x * blockDim.x + threadIdx.x;
    if (ch >= B * D) return;
    int b = ch / D, d = ch % D;
    float cur = h0[ch];
    for (int c = 0; c < SC_NC; c++) {
        size_t o = ((size_t)b * SC_NC + c) * D + d;
        carry[o] = cur;
        cur = fmaf(aend[o], cur, hend[o]);
    }
    if (hlast) hlast[ch] = cur;
}

// ---------------- scan pass3 ----------------
__global__ void scan_pass3(const __half* __restrict__ omah, const __half* __restrict__ gbh,
                           const float* __restrict__ carry, const __half* __restrict__ yA,
                           __half* __restrict__ zA)
{
    using namespace hk;
    int t = blockIdx.x * blockDim.x + threadIdx.x;
    if (t >= B * SC_NC * D) return;
    int d = t % D;
    int c = (t / D) % SC_NC;
    int b = t / (D * SC_NC);
    float h = carry[((size_t)b * SC_NC + c) * D + d];
    size_t g = ((size_t)b * S + (size_t)c * SC_L) * D + d;
    for (int i = 0; i < SC_L; i++, g += D) {
        float a = 1.0f - __half2float(omah[g]);
        h = fmaf(a, h, __half2float(gbh[g]));
        zA[g] = __float2half_rn(__half2float(yA[g]) * h);
    }
}

// =====================================================================
// host-side tensormap encoding (driver symbol via dlsym)
// =====================================================================
typedef CUresult (*EncodeFn)(CUtensorMap*, CUtensorMapDataType, cuuint32_t, void*,
                             const cuuint64_t*, const cuuint64_t*, const cuuint32_t*,
                             const cuuint32_t*, CUtensorMapInterleave, CUtensorMapSwizzle,
                             CUtensorMapL2promotion, CUtensorMapFloatOOBfill);

static EncodeFn get_encode() {
    static EncodeFn fn = nullptr;
    if (!fn) {
        fn = (EncodeFn)dlsym(RTLD_DEFAULT, "cuTensorMapEncodeTiled");
        if (!fn) {
            void* h = dlopen("libcuda.so.1", RTLD_LAZY | RTLD_GLOBAL);
            if (h) fn = (EncodeFn)dlsym(h, "cuTensorMapEncodeTiled");
        }
    }
    return fn;
}

static void enc_map(CUtensorMap* m, void* ptr, uint64_t K, uint64_t ROWS, uint32_t boxRows) {
    cuuint64_t dims[2]    = {K, ROWS};
    cuuint64_t strides[1] = {K * 2};
    cuuint32_t box[2]     = {32, boxRows};
    cuuint32_t es[2]      = {1, 1};
    get_encode()(m, CU_TENSOR_MAP_DATA_TYPE_FLOAT16, 2, ptr, dims, strides, box, es,
                 CU_TENSOR_MAP_INTERLEAVE_NONE, CU_TENSOR_MAP_SWIZZLE_64B,
                 CU_TENSOR_MAP_L2_PROMOTION_L2_128B, CU_TENSOR_MAP_FLOAT_OOB_FILL_NONE);
}

// ---------------- launch ----------------
extern "C" void kernel_launch(void* const* d_in, const int* in_sizes, int n_in,
                              void* d_out, int out_size)
{
    using namespace hk;
    const float* x    = (const float*)d_in[0];
    const float* h0   = (const float*)d_in[1];
    const float* r1w  = (const float*)d_in[2];
    const float* r2w  = (const float*)d_in[3];
    const float* Wx   = (const float*)d_in[4];
    const float* Wy   = (const float*)d_in[5];
    const float* cw   = (const float*)d_in[6];
    const float* cb   = (const float*)d_in[7];
    const float* apar = (const float*)d_in[8];
    const float* igw  = (const float*)d_in[9];
    const float* igb  = (const float*)d_in[10];
    const float* agw  = (const float*)d_in[11];
    const float* agb  = (const float*)d_in[12];
    const float* Wout = (const float*)d_in[13];
    const float* Wg   = (const float*)d_in[14];
    const float* Wu   = (const float*)d_in[15];
    const float* Wd   = (const float*)d_in[16];
    float* out = (float*)d_out;

    float *resid, *hend, *aend, *carry;
    cudaGetSymbolAddress((void**)&resid, g_resid);
    cudaGetSymbolAddress((void**)&hend,  g_hend);
    cudaGetSymbolAddress((void**)&aend,  g_aend);
    cudaGetSymbolAddress((void**)&carry, g_carry);

    __half *omah,*gbh,*nA,*yA,*xbh,*xcH,*zA,*n2A,*GA,*guA;
    __half *tWyx,*tWo,*tWg,*tWu,*tWd,*aWH,*iWH;
    cudaGetSymbolAddress((void**)&omah, g_omah);
    cudaGetSymbolAddress((void**)&gbh, g_gbh);
    cudaGetSymbolAddress((void**)&nA,  g_nA);
    cudaGetSymbolAddress((void**)&yA,  g_yA);
    cudaGetSymbolAddress((void**)&xbh, g_xbh);
    cudaGetSymbolAddress((void**)&xcH, g_xcH);
    cudaGetSymbolAddress((void**)&zA,  g_zA);
    cudaGetSymbolAddress((void**)&n2A, g_n2A);
    cudaGetSymbolAddress((void**)&GA,  g_GA);
    cudaGetSymbolAddress((void**)&guA, g_guA);
    cudaGetSymbolAddress((void**)&tWyx, g_Wyx);
    cudaGetSymbolAddress((void**)&tWo, g_Wo);  cudaGetSymbolAddress((void**)&tWg, g_Wg);
    cudaGetSymbolAddress((void**)&tWu, g_Wu);  cudaGetSymbolAddress((void**)&tWd, g_Wd);
    cudaGetSymbolAddress((void**)&aWH, g_aWH); cudaGetSymbolAddress((void**)&iWH, g_iWH);

    // ---- tensormaps ----
    static CUtensorMap mnA, mzA, mn2A, mguA;
    static CUtensorMap mWyx, mWo, mWg, mWu, mWd;
    static CUtensorMap mXh, mWaH, mWiH;
    enc_map(&mnA,  nA,  D, BS, 128);
    enc_map(&mzA,  zA,  D, BS, 128);
    enc_map(&mn2A, n2A, D, BS, 128);
    enc_map(&mguA, guA, F, BS, 128);
    enc_map(&mWyx, tWyx, D, 2 * (uint64_t)D, 256);
    enc_map(&mWo,  tWo, D, D, 256);   enc_map(&mWg,  tWg, D, F, 256);
    enc_map(&mWu,  tWu, D, F, 256);   enc_map(&mWd,  tWd, F, D, 256);
    enc_map(&mXh,  xcH, D, BS, 128);
    enc_map(&mWaH, aWH, HD, (uint64_t)H * HD, 128);
    enc_map(&mWiH, iWH, HD, (uint64_t)H * HD, 128);

    cudaFuncSetAttribute(gemm_tma<2>, cudaFuncAttributeMaxDynamicSharedMemorySize, GT_SMEM);
    cudaFuncSetAttribute(gemm_tma<3>, cudaFuncAttributeMaxDynamicSharedMemorySize, GT_SMEM);
    cudaFuncSetAttribute(gemm_tma<4>, cudaFuncAttributeMaxDynamicSharedMemorySize, GT_SMEM);
    cudaFuncSetAttribute(gemm_dual,   cudaFuncAttributeMaxDynamicSharedMemorySize, GT_SMEM);
    cudaFuncSetAttribute(gate_mma,    cudaFuncAttributeMaxDynamicSharedMemorySize, GG_SMEM);

    float* hlast = (out_size >= (int)(NBSD + (size_t)B * D)) ? (out + NBSD) : nullptr;

    // ---- weight transpose/convert ----
    trans_all<<<15360, 256>>>(Wy, tWyx, Wx, tWyx + NDD, Wout, tWo,
                              Wg, tWg, Wu, tWu, Wd, tWd);
    trans_gate2<<<dim3(HD / 32, HD / 32, 2 * H), dim3(32, 8)>>>(agw, aWH, igw, iWH);

    // ---- temporal pre-norm (vectorized) ----
    rmsnorm_v<<<BS, 256>>>(x, r1w, nA);

    // ---- combined: y = gelu(nA @ Wy) fp16 AND xb = nA @ Wx fp16 ----
    dim3 gDual(2 * D / 256, BS / 128);
    gemm_dual<<<gDual, GT_THR, GT_SMEM>>>(mnA, mWyx, yA, xbh, D, D);

    // ---- causal conv (vectorized) ----
    conv_v<<<(unsigned)(NBSD / 8 / 256), 256>>>(xbh, cw, cb, xcH);

    // ---- fused gate GEMM + gate math + chunk-end scan ----
    gate_mma<<<dim3(BS / 128, H), 256, GG_SMEM>>>(mXh, mWaH, mWiH,
                                                  agb, igb, apar, omah, gbh, hend, aend);

    // ---- carries + final rescan fused with y-mul ----
    scan_pass2<<<(B * D + 255) / 256, 256>>>(hend, aend, h0, carry, hlast);
    scan_pass3<<<(B * SC_NC * D + 255) / 256, 256>>>(omah, gbh, carry, yA, zA);

    // ---- residual = z @ W_out + x ----
    dim3 gDD(D / 256, BS / 128);
    gemm_tma<2><<<gDD, GT_THR, GT_SMEM>>>(mzA, mWo, resid, x, nullptr, nullptr, D, D);

    // ---- second norm (vectorized) ----
    rmsnorm_v<<<BS, 256>>>(resid, r2w, n2A);

    // ---- MLP: G = gelu(n2 @ Wg) fp16; gu = (n2 @ Wu) * G fp16 ----
    dim3 gDF(F / 256, BS / 128);
    gemm_tma<4><<<gDF, GT_THR, GT_SMEM>>>(mn2A, mWg, nullptr, nullptr, nullptr, GA, F, D);
    gemm_tma<3><<<gDF, GT_THR, GT_SMEM>>>(mn2A, mWu, nullptr, nullptr, GA, guA, F, D);

    // ---- out = gu @ W_down + residual ----
    gemm_tma<2><<<gDD, GT_THR, GT_SMEM>>>(mguA, mWd, out, resid, nullptr, nullptr, D, F);
}

// round 17
// speedup vs baseline: 1.0927x; 1.0246x over previous
#include <cuda_runtime.h>
#include <cuda.h>
#include <cuda_fp16.h>
#include <math.h>
#include <stdint.h>
#include <dlfcn.h>

// ---------------- problem constants ----------------
namespace hk {
constexpr int B  = 2;
constexpr int S  = 2048;
constexpr int D  = 2048;
constexpr int H  = 16;
constexpr int HD = 128;
constexpr int F  = 8192;
constexpr int BS = B * S;                     // 4096 rows
constexpr size_t NBSD = (size_t)BS * D;       // 8,388,608
constexpr size_t NBSF = (size_t)BS * F;       // 33,554,432
constexpr size_t NDD  = (size_t)D * D;
constexpr size_t NDF  = (size_t)D * F;
constexpr size_t NGW  = (size_t)H * HD * HD;  // 262,144
}

constexpr int SC_NC = 16;                      // scan chunks
constexpr int SC_L  = hk::S / SC_NC;           // 128 steps per chunk

// ---------------- scratch: fp32 intermediates ----------------
__device__ float g_resid [hk::NBSD];
__device__ float g_hend  [hk::B * hk::D * SC_NC];
__device__ float g_aend  [hk::B * hk::D * SC_NC];
__device__ float g_carry [hk::B * hk::D * SC_NC];

// ---------------- scratch: fp16 activations ----------------
__device__ __half g_omah[hk::NBSD];            // 1 - a
__device__ __half g_gbh [hk::NBSD];            // b
__device__ __half g_nA  [hk::NBSD];
__device__ __half g_yA  [hk::NBSD];
__device__ __half g_xbh [hk::NBSD];
__device__ __half g_xcH [hk::NBSD];
__device__ __half g_zA  [hk::NBSD];
__device__ __half g_n2A [hk::NBSD];
__device__ __half g_GA  [hk::NBSF];
__device__ __half g_guA [hk::NBSF];

// ---------------- scratch: fp16 transposed weights [N,K] ----------------
__device__ __half g_Wyx[2 * hk::NDD];          // [Wy ; Wx] concatenated on N
__device__ __half g_Wo[hk::NDD];
__device__ __half g_Wg[hk::NDF];
__device__ __half g_Wu[hk::NDF];
__device__ __half g_Wd[hk::NDF];
// gate weights, transposed per head [H][e][d], single fp16
__device__ __half g_aWH[hk::NGW];
__device__ __half g_iWH[hk::NGW];

// ---------------- helpers ----------------
__device__ __forceinline__ float gelu_tanh(float x) {
    float x3 = x * x * x;
    return 0.5f * x * (1.0f + tanhf(0.7978845608028654f * (x + 0.044715f * x3)));
}

__device__ __forceinline__ uint32_t s2u(const void* p) {
    uint32_t a;
    asm("{ .reg .u64 t; cvta.to.shared.u64 t, %1; cvt.u32.u64 %0, t; }" : "=r"(a) : "l"(p));
    return a;
}

__device__ __forceinline__ void ldmx4(uint32_t* r, uint32_t a) {
    asm volatile("ldmatrix.sync.aligned.m8n8.x4.shared.b16 {%0,%1,%2,%3}, [%4];"
                 : "=r"(r[0]), "=r"(r[1]), "=r"(r[2]), "=r"(r[3]) : "r"(a));
}

__device__ __forceinline__ void mma16816(float* c, const uint32_t* a, const uint32_t* b) {
    asm volatile(
        "mma.sync.aligned.m16n8k16.row.col.f32.f16.f16.f32 "
        "{%0,%1,%2,%3}, {%4,%5,%6,%7}, {%8,%9}, {%0,%1,%2,%3};"
        : "+f"(c[0]), "+f"(c[1]), "+f"(c[2]), "+f"(c[3])
        : "r"(a[0]), "r"(a[1]), "r"(a[2]), "r"(a[3]), "r"(b[0]), "r"(b[1]));
}

__device__ __forceinline__ void mbar_init(uint32_t mbar, uint32_t cnt) {
    asm volatile("mbarrier.init.shared.b64 [%0], %1;" :: "r"(mbar), "r"(cnt) : "memory");
}

__device__ __forceinline__ void mbar_expect_tx(uint32_t mbar, uint32_t bytes) {
    asm volatile("mbarrier.arrive.expect_tx.shared.b64 _, [%0], %1;"
                 :: "r"(mbar), "r"(bytes) : "memory");
}

__device__ __forceinline__ void mbar_wait(uint32_t mbar, uint32_t phase) {
    asm volatile(
        "{\n\t.reg .pred P;\n\t"
        "WAIT_%=:\n\t"
        "mbarrier.try_wait.parity.shared.b64 P, [%0], %1, 10000000;\n\t"
        "@P bra.uni DONE_%=;\n\t"
        "bra.uni WAIT_%=;\n\t"
        "DONE_%=:\n\t}"
        :: "r"(mbar), "r"(phase) : "memory");
}

__device__ __forceinline__ void tma2d(uint32_t dst, const CUtensorMap* map,
                                      int cx, int cy, uint32_t mbar) {
    asm volatile(
        "cp.async.bulk.tensor.2d.shared::cluster.global.tile.mbarrier::complete_tx::bytes "
        "[%0], [%1, {%2, %3}], [%4];"
        :: "r"(dst), "l"(map), "r"(cx), "r"(cy), "r"(mbar) : "memory");
}

// =====================================================================
// GEMM core: 256 threads (8 warps 2x4, 64x64 warp tile), CTA tile
// 128x256, TMA (SW64), 8-stage pipeline, sync every 4 K-blocks,
// FRAGMENT DOUBLE-BUFFERING: while MMAs for one half-K-step run, the
// fragments for the next half-step (and the next block's mbar wait)
// are overlapped. Per-element accumulation order unchanged.
// =====================================================================
constexpr int GT_NSTG  = 8;
constexpr int GT_TA    = 128 * 64;              // 8192 B A tile
constexpr int GT_TB    = 256 * 64;              // 16384 B B tile
constexpr int GT_STAGE = GT_TA + GT_TB;         // 24576 B
constexpr int GT_HDR   = 1024;
constexpr int GT_SMEM  = GT_HDR + GT_NSTG * GT_STAGE;   // 197632 B
constexpr int GT_THR   = 256;

#define GEMM_MAINLOOP(mA_, mB_)                                                   \
    const uint32_t sb    = s2u(smem);                                             \
    const uint32_t tiles = sb + GT_HDR;                                           \
    const int tid  = threadIdx.x;                                                 \
    const int lane = tid & 31;                                                    \
    const int wid  = tid >> 5;                                                    \
    const int wm   = wid >> 2;        /* 0..1 -> 64-row slab */                   \
    const int wn   = wid & 3;         /* 0..3 -> 64-col slab */                   \
    const int row0 = blockIdx.y * 128;                                            \
    const int col0 = blockIdx.x * 256;                                            \
    const int KB   = K >> 5;                                                      \
    if (tid == 0) {                                                               \
        _Pragma("unroll")                                                         \
        for (int s = 0; s < GT_NSTG; s++) mbar_init(sb + s * 8, 1);               \
    }                                                                             \
    __syncthreads();                                                              \
    uint32_t arow[4], axm[4], brow[4], bxm[4];                                    \
    _Pragma("unroll")                                                             \
    for (int im = 0; im < 4; im++) {                                              \
        int r = wm * 64 + im * 16 + (lane & 15);                                  \
        arow[im] = (uint32_t)(r * 64);                                            \
        axm[im]  = (uint32_t)((r & 6) << 3);                                      \
    }                                                                             \
    _Pragma("unroll")                                                             \
    for (int ip = 0; ip < 4; ip++) {                                              \
        int r = wn * 64 + ip * 16 + (lane & 7) + ((lane >> 4) & 1) * 8;           \
        brow[ip] = (uint32_t)(r * 64);                                            \
        bxm[ip]  = (uint32_t)((r & 6) << 3);                                      \
    }                                                                             \
    const uint32_t acol = (uint32_t)((lane >> 4) * 16);                           \
    const uint32_t bcol = (uint32_t)(((lane >> 3) & 1) * 16);                     \
    float acc[4][8][4];                                                           \
    _Pragma("unroll")                                                             \
    for (int im = 0; im < 4; im++)                                                \
        _Pragma("unroll")                                                         \
        for (int in = 0; in < 8; in++)                                            \
            _Pragma("unroll")                                                     \
            for (int q = 0; q < 4; q++) acc[im][in][q] = 0.0f;                    \
    uint32_t afb[2][4][4], bfb[2][8][2];                                          \
    auto issue = [&](int kb) {                                                    \
        int slot = kb & (GT_NSTG - 1);                                            \
        uint32_t bar = sb + slot * 8;                                             \
        uint32_t st  = tiles + (uint32_t)slot * GT_STAGE;                         \
        mbar_expect_tx(bar, (uint32_t)GT_STAGE);                                  \
        tma2d(st,         &mA_, kb * 32, row0, bar);                              \
        tma2d(st + GT_TA, &mB_, kb * 32, col0, bar);                              \
    };                                                                            \
    auto ldfrag = [&](int buf, int kb, int kk) {                                  \
        const uint32_t sA = tiles + (uint32_t)(kb & (GT_NSTG - 1)) * GT_STAGE;    \
        const uint32_t sB = sA + GT_TA;                                           \
        _Pragma("unroll")                                                         \
        for (int im = 0; im < 4; im++) {                                          \
            uint32_t rest = (acol + (uint32_t)(kk * 32)) ^ axm[im];               \
            ldmx4(afb[buf][im], sA + arow[im] + rest);                            \
        }                                                                         \
        _Pragma("unroll")                                                         \
        for (int ip = 0; ip < 4; ip++) {                                          \
            uint32_t rest = (bcol + (uint32_t)(kk * 32)) ^ bxm[ip];               \
            uint32_t r4[4];                                                       \
            ldmx4(r4, sB + brow[ip] + rest);                                      \
            bfb[buf][2 * ip + 0][0] = r4[0]; bfb[buf][2 * ip + 0][1] = r4[1];     \
            bfb[buf][2 * ip + 1][0] = r4[2]; bfb[buf][2 * ip + 1][1] = r4[3];     \
        }                                                                         \
    };                                                                            \
    auto mmastep = [&](int buf) {                                                 \
        _Pragma("unroll")                                                         \
        for (int im = 0; im < 4; im++)                                            \
            _Pragma("unroll")                                                     \
            for (int in = 0; in < 8; in++)                                        \
                mma16816(acc[im][in], afb[buf][im], bfb[buf][in]);                \
    };                                                                            \
    if (tid == 0) {                                                               \
        _Pragma("unroll")                                                         \
        for (int s = 0; s < GT_NSTG - 1; s++) issue(s);                           \
    }                                                                             \
    mbar_wait(sb + 0, 0u);                                                        \
    ldfrag(0, 0, 0);                                                              \
    for (int kb = 0; kb < KB; kb += 4) {                                          \
        _Pragma("unroll")                                                         \
        for (int j = 0; j < 4; j++) {                                             \
            int k = kb + j;                                                       \
            ldfrag(1, k, 1);            /* kk1 frags while kk0 MMAs run */        \
            mmastep(0);                 /* (k, kk0) */                            \
            if (k + 1 < KB) {                                                     \
                mbar_wait(sb + (((k + 1) & (GT_NSTG - 1)) * 8),                   \
                          (uint32_t)(((k + 1) / GT_NSTG) & 1));                   \
                ldfrag(0, k + 1, 0);    /* next block kk0 while kk1 MMAs run */   \
            }                                                                     \
            mmastep(1);                 /* (k, kk1) */                            \
        }                                                                         \
        __syncthreads();                                                          \
        if (tid == 0) {                                                           \
            _Pragma("unroll")                                                     \
            for (int j = 0; j < 4; j++)                                           \
                if (kb + GT_NSTG - 1 + j < KB) issue(kb + GT_NSTG - 1 + j);       \
        }                                                                         \
    }

// =====================================================================
// gemm_tma: EPI 2 add aux fp32 -> C fp32; 3 mul auxh fp16 -> OH fp16;
//           4 gelu -> OH fp16.
// =====================================================================
template<int EPI>
__global__ void __launch_bounds__(GT_THR, 1)
gemm_tma(const __grid_constant__ CUtensorMap mA,
         const __grid_constant__ CUtensorMap mB,
         float* __restrict__ C, const float* __restrict__ aux,
         const __half* __restrict__ auxh, __half* __restrict__ OH,
         int N, int K)
{
    extern __shared__ __align__(1024) char smem[];
    GEMM_MAINLOOP(mA, mB)

    const int gid = lane >> 2, t4 = lane & 3;
    #pragma unroll
    for (int im = 0; im < 4; im++) {
        #pragma unroll
        for (int in = 0; in < 8; in++) {
            int r = row0 + wm * 64 + im * 16 + gid;
            int c = col0 + wn * 64 + in * 8 + t4 * 2;
            #pragma unroll
            for (int half = 0; half < 2; half++) {
                int rr = r + half * 8;
                float v0 = acc[im][in][half * 2 + 0];
                float v1 = acc[im][in][half * 2 + 1];
                if (EPI == 2) {
                    float2 a2 = *reinterpret_cast<const float2*>(aux + (size_t)rr * N + c);
                    v0 += a2.x; v1 += a2.y;
                    float2 o; o.x = v0; o.y = v1;
                    *reinterpret_cast<float2*>(C + (size_t)rr * N + c) = o;
                } else if (EPI == 3) {
                    __half2 a2 = *reinterpret_cast<const __half2*>(auxh + (size_t)rr * N + c);
                    v0 *= __half2float(a2.x); v1 *= __half2float(a2.y);
                    __half2 hp; hp.x = __float2half_rn(v0); hp.y = __float2half_rn(v1);
                    *reinterpret_cast<__half2*>(OH + (size_t)rr * N + c) = hp;
                } else {   // EPI == 4: gelu
                    v0 = gelu_tanh(v0); v1 = gelu_tanh(v1);
                    __half2 hp; hp.x = __float2half_rn(v0); hp.y = __float2half_rn(v1);
                    *reinterpret_cast<__half2*>(OH + (size_t)rr * N + c) = hp;
                }
            }
        }
    }
}

// =====================================================================
// gemm_dual: combined Wy+Wx GEMM over concatenated B [2*NOUT, K].
// =====================================================================
__global__ void __launch_bounds__(GT_THR, 1)
gemm_dual(const __grid_constant__ CUtensorMap mA,
          const __grid_constant__ CUtensorMap mB,
          __half* __restrict__ O1, __half* __restrict__ O2,
          int NOUT, int K)
{
    extern __shared__ __align__(1024) char smem[];
    GEMM_MAINLOOP(mA, mB)

    const bool side = (col0 >= NOUT);
    __half* dst = side ? O2 : O1;
    const int cb0 = side ? (col0 - NOUT) : col0;

    const int gid = lane >> 2, t4 = lane & 3;
    #pragma unroll
    for (int im = 0; im < 4; im++) {
        #pragma unroll
        for (int in = 0; in < 8; in++) {
            int r = row0 + wm * 64 + im * 16 + gid;
            int c = cb0 + wn * 64 + in * 8 + t4 * 2;
            #pragma unroll
            for (int half = 0; half < 2; half++) {
                int rr = r + half * 8;
                float v0 = acc[im][in][half * 2 + 0];
                float v1 = acc[im][in][half * 2 + 1];
                if (!side) { v0 = gelu_tanh(v0); v1 = gelu_tanh(v1); }
                __half2 hp; hp.x = __float2half_rn(v0); hp.y = __float2half_rn(v1);
                *reinterpret_cast<__half2*>(dst + (size_t)rr * NOUT + c) = hp;
            }
        }
    }
}

// =====================================================================
// gate_mma (unchanged winner)
// =====================================================================
constexpr int GG_CH   = 8192;
constexpr int GG_MAT  = 4 * GG_CH;
constexpr int GG_HDR  = 1024;
constexpr int GG_ASP  = GG_HDR + GG_MAT;
constexpr int GG_BSP  = GG_HDR + 3 * GG_MAT;
constexpr int GG_SMEM = GG_BSP + 32768;       // 132096 B

__global__ void __launch_bounds__(256, 1)
gate_mma(const __grid_constant__ CUtensorMap mXh,
         const __grid_constant__ CUtensorMap mWaH,
         const __grid_constant__ CUtensorMap mWiH,
         const float* __restrict__ ab, const float* __restrict__ ib,
         const float* __restrict__ apar,
         __half* __restrict__ omah, __half* __restrict__ gbh,
         float* __restrict__ hend, float* __restrict__ aend)
{
    using namespace hk;
    extern __shared__ __align__(1024) char smem[];
    const uint32_t sb    = s2u(smem);
    const uint32_t tiles = sb + GG_HDR;

    const int tid  = threadIdx.x;
    const int lane = tid & 31;
    const int wid  = tid >> 5;
    const int wm   = wid >> 2;
    const int wn   = wid & 3;
    const int row0 = blockIdx.x * 128;
    const int h    = blockIdx.y;

    float* asp = reinterpret_cast<float*>(smem + GG_ASP);
    __half* bsp = reinterpret_cast<__half*>(smem + GG_BSP);

    if (tid == 0) mbar_init(sb, 1);
    __syncthreads();

    if (tid == 0) {
        mbar_expect_tx(sb, (uint32_t)(3 * GG_MAT));
        #pragma unroll
        for (int c = 0; c < 4; c++) {
            int kx = c * 32;
            tma2d(tiles + 0 * GG_MAT + c * GG_CH, &mXh,  h * HD + kx, row0,   sb);
            tma2d(tiles + 1 * GG_MAT + c * GG_CH, &mWaH, kx,          h * HD, sb);
            tma2d(tiles + 2 * GG_MAT + c * GG_CH, &mWiH, kx,          h * HD, sb);
        }
    }
    mbar_wait(sb, 0);
    __syncthreads();

    uint32_t arow[4], axm[4], brow[2], bxm[2];
    #pragma unroll
    for (int im = 0; im < 4; im++) {
        int r = wm * 64 + im * 16 + (lane & 15);
        arow[im] = (uint32_t)(r * 64);
        axm[im]  = (uint32_t)((r & 6) << 3);
    }
    #pragma unroll
    for (int ip = 0; ip < 2; ip++) {
        int r = wn * 32 + ip * 16 + (lane & 7) + ((lane >> 4) & 1) * 8;
        brow[ip] = (uint32_t)(r * 64);
        bxm[ip]  = (uint32_t)((r & 6) << 3);
    }
    const uint32_t acol = (uint32_t)((lane >> 4) * 16);
    const uint32_t bcol = (uint32_t)(((lane >> 3) & 1) * 16);

    float accR[4][4][4], accI[4][4][4];
    #pragma unroll
    for (int im = 0; im < 4; im++)
        #pragma unroll
        for (int in = 0; in < 4; in++)
            #pragma unroll
            for (int q = 0; q < 4; q++) { accR[im][in][q] = 0.0f; accI[im][in][q] = 0.0f; }

    #pragma unroll
    for (int c = 0; c < 4; c++) {
        const uint32_t sAh = tiles + 0 * GG_MAT + c * GG_CH;
        const uint32_t sWa = tiles + 1 * GG_MAT + c * GG_CH;
        const uint32_t sWi = tiles + 2 * GG_MAT + c * GG_CH;
        #pragma unroll
        for (int kk = 0; kk < 2; kk++) {
            uint32_t af[4][4], wa[4][2], wi[4][2];
            #pragma unroll
            for (int im = 0; im < 4; im++) {
                uint32_t rest = (acol + (uint32_t)(kk * 32)) ^ axm[im];
                ldmx4(af[im], sAh + arow[im] + rest);
            }
            #pragma unroll
            for (int ip = 0; ip < 2; ip++) {
                uint32_t rest = (bcol + (uint32_t)(kk * 32)) ^ bxm[ip];
                uint32_t r4[4];
                ldmx4(r4, sWa + brow[ip] + rest);
                wa[2*ip][0]=r4[0]; wa[2*ip][1]=r4[1]; wa[2*ip+1][0]=r4[2]; wa[2*ip+1][1]=r4[3];
                ldmx4(r4, sWi + brow[ip] + rest);
                wi[2*ip][0]=r4[0]; wi[2*ip][1]=r4[1]; wi[2*ip+1][0]=r4[2]; wi[2*ip+1][1]=r4[3];
            }
            #pragma unroll
            for (int im = 0; im < 4; im++)
                #pragma unroll
                for (int in = 0; in < 4; in++) {
                    mma16816(accR[im][in], af[im], wa[in]);
                    mma16816(accI[im][in], af[im], wi[in]);
                }
        }
    }
    __syncthreads();

    const int gid = lane >> 2, t4 = lane & 3;
    #pragma unroll
    for (int in = 0; in < 4; in++) {
        int c0 = wn * 32 + in * 8 + t4 * 2;
        #pragma unroll
        for (int q = 0; q < 2; q++) {
            int col = c0 + q;
            int dd  = h * HD + col;
            float ab_ = ab[dd], ib_ = ib[dd];
            float sp  = log1pf(expf(-apar[dd]));
            int cch = col >> 5;
            uint32_t cb = (uint32_t)((col & 31) * 2);
            uint32_t cbase = (uint32_t)(cch * GG_CH);
            #pragma unroll
            for (int im = 0; im < 4; im++) {
                #pragma unroll
                for (int half = 0; half < 2; half++) {
                    int row = wm * 64 + im * 16 + gid + half * 8;
                    float rv = accR[im][in][half * 2 + q] + ab_;
                    float iv = accI[im][in][half * 2 + q] + ib_;
                    float r  = 1.0f / (1.0f + expf(-rv));
                    float ii = 1.0f / (1.0f + expf(-iv));
                    float la = -8.0f * r * sp;
                    float a  = expf(la);
                    __half omh = __float2half_rn(1.0f - a);
                    float aq = 1.0f - __half2float(omh);
                    float mult = sqrtf(fmaxf(1.0f - expf(2.0f * la), 0.0f));
                    uint32_t off = cbase + (uint32_t)(row * 64)
                                 + ((cb & 48u) ^ (uint32_t)((row & 6) << 3)) + (cb & 15u);
                    float xcv = __half2float(*reinterpret_cast<const __half*>(
                                    smem + GG_HDR + off));
                    __half bh = __float2half_rn(mult * ii * xcv);
                    size_t g = (size_t)(row0 + row) * D + dd;
                    omah[g] = omh;
                    gbh[g]  = bh;
                    int sidx = row * 128 + (col ^ (row & 31));
                    asp[sidx] = aq;
                    bsp[sidx] = bh;
                }
            }
        }
    }
    __syncthreads();

    if (tid < 128) {
        int col = tid;
        float hh = 0.0f, A = 1.0f;
        #pragma unroll 4
        for (int row = 0; row < 128; row++) {
            int sidx = row * 128 + (col ^ (row & 31));
            float a = asp[sidx];
            hh = fmaf(a, hh, __half2float(bsp[sidx]));
            A *= a;
        }
        int bb = row0 / S;
        int cc = (row0 % S) / SC_L;
        size_t o = ((size_t)bb * SC_NC + cc) * D + (size_t)h * HD + col;
        hend[o] = hh;
        aend[o] = A;
    }
}

// =====================================================================
// combined weight transpose/convert
// =====================================================================
__global__ void __launch_bounds__(256)
trans_all(const float* __restrict__ W0, __half* __restrict__ T0,
          const float* __restrict__ W1, __half* __restrict__ T1,
          const float* __restrict__ W2, __half* __restrict__ T2,
          const float* __restrict__ W3, __half* __restrict__ T3,
          const float* __restrict__ W4, __half* __restrict__ T4,
          const float* __restrict__ W5, __half* __restrict__ T5)
{
    using namespace hk;
    __shared__ float t[64][65];
    int b = blockIdx.x;
    const float* W; __half* Wt; int K, N, lb;
    if      (b < 1024)  { W = W0; Wt = T0; K = D; N = D; lb = b; }
    else if (b < 2048)  { W = W1; Wt = T1; K = D; N = D; lb = b - 1024; }
    else if (b < 3072)  { W = W2; Wt = T2; K = D; N = D; lb = b - 2048; }
    else if (b < 7168)  { W = W3; Wt = T3; K = D; N = F; lb = b - 3072; }
    else if (b < 11264) { W = W4; Wt = T4; K = D; N = F; lb = b - 7168; }
    else                { W = W5; Wt = T5; K = F; N = D; lb = b - 11264; }
    int nbx = N >> 6;
    int n0 = (lb % nbx) * 64, k0 = (lb / nbx) * 64;

    int tid = threadIdx.x;
    int lr = tid >> 4;
    int lc = (tid & 15) * 4;
    #pragma unroll
    for (int i = 0; i < 4; i++) {
        int r = lr + i * 16;
        float4 v = *reinterpret_cast<const float4*>(&W[(size_t)(k0 + r) * N + n0 + lc]);
        t[r][lc] = v.x; t[r][lc + 1] = v.y; t[r][lc + 2] = v.z; t[r][lc + 3] = v.w;
    }
    __syncthreads();
    #pragma unroll
    for (int i = 0; i < 2; i++) {
        int task = tid + i * 256;
        int n  = task >> 3;
        int kg = (task & 7) * 8;
        __half h8[8];
        #pragma unroll
        for (int j = 0; j < 8; j++) h8[j] = __float2half_rn(t[kg + j][n]);
        *reinterpret_cast<uint4*>(&Wt[(size_t)(n0 + n) * K + k0 + kg]) =
            *reinterpret_cast<uint4*>(h8);
    }
}

// gate-weight transpose: both weights in one launch (z in [0, 2H))
__global__ void trans_gate2(const float* __restrict__ Wa, __half* __restrict__ Ta,
                            const float* __restrict__ Wi, __half* __restrict__ Ti)
{
    using namespace hk;
    __shared__ float t[32][33];
    int e0 = blockIdx.x * 32, d0 = blockIdx.y * 32;
    int z = blockIdx.z;
    int hh = z & (H - 1);
    const float* W = (z < H) ? Wa : Wi;
    __half* T = (z < H) ? Ta : Ti;
    int tx = threadIdx.x, ty = threadIdx.y;
    const float* Wh = W + (size_t)hh * HD * HD;
    #pragma unroll
    for (int i = 0; i < 32; i += 8)
        t[ty + i][tx] = Wh[(size_t)(d0 + ty + i) * HD + (e0 + tx)];
    __syncthreads();
    #pragma unroll
    for (int i = 0; i < 32; i += 8) {
        size_t o = ((size_t)hh * HD + (e0 + ty + i)) * HD + (d0 + tx);
        T[o] = __float2half_rn(t[tx][ty + i]);
    }
}

// ---------------- vectorized rmsnorm ----------------
__global__ void __launch_bounds__(256)
rmsnorm_v(const float* __restrict__ x, const float* __restrict__ w,
          __half* __restrict__ o)
{
    using namespace hk;
    const int row = blockIdx.x;
    const int tid = threadIdx.x;
    const float4* xr = reinterpret_cast<const float4*>(x + (size_t)row * D);
    float4 v0 = xr[tid * 2];
    float4 v1 = xr[tid * 2 + 1];
    float ss = v0.x*v0.x + v0.y*v0.y + v0.z*v0.z + v0.w*v0.w
             + v1.x*v1.x + v1.y*v1.y + v1.z*v1.z + v1.w*v1.w;
    __shared__ float red[8];
    #pragma unroll
    for (int off = 16; off > 0; off >>= 1) ss += __shfl_down_sync(0xffffffffu, ss, off);
    if ((tid & 31) == 0) red[tid >> 5] = ss;
    __syncthreads();
    if (tid < 8) {
        float v = red[tid];
        #pragma unroll
        for (int off = 4; off > 0; off >>= 1) v += __shfl_down_sync(0xffu, v, off);
        if (tid == 0) red[0] = v;
    }
    __syncthreads();
    const float scale = rsqrtf(red[0] / (float)D + 1e-6f);
    const float4* wr = reinterpret_cast<const float4*>(w);
    float4 w0 = wr[tid * 2];
    float4 w1 = wr[tid * 2 + 1];
    __half h8[8];
    h8[0] = __float2half_rn(v0.x * scale * w0.x);
    h8[1] = __float2half_rn(v0.y * scale * w0.y);
    h8[2] = __float2half_rn(v0.z * scale * w0.z);
    h8[3] = __float2half_rn(v0.w * scale * w0.w);
    h8[4] = __float2half_rn(v1.x * scale * w1.x);
    h8[5] = __float2half_rn(v1.y * scale * w1.y);
    h8[6] = __float2half_rn(v1.z * scale * w1.z);
    h8[7] = __float2half_rn(v1.w * scale * w1.w);
    *reinterpret_cast<uint4*>(o + (size_t)row * D + tid * 8) =
        *reinterpret_cast<uint4*>(h8);
}

// ---------------- vectorized causal conv ----------------
__global__ void __launch_bounds__(256)
conv_v(const __half* __restrict__ xbh, const float* __restrict__ cw,
       const float* __restrict__ cb, __half* __restrict__ xcH)
{
    using namespace hk;
    size_t t = (size_t)blockIdx.x * blockDim.x + threadIdx.x;
    size_t base = t * 8;
    if (base >= NBSD) return;
    int d = (int)(base % D);
    int s = (int)((base / D) % S);
    float acc[8];
    {
        float4 c0 = *reinterpret_cast<const float4*>(cb + d);
        float4 c1 = *reinterpret_cast<const float4*>(cb + d + 4);
        acc[0]=c0.x; acc[1]=c0.y; acc[2]=c0.z; acc[3]=c0.w;
        acc[4]=c1.x; acc[5]=c1.y; acc[6]=c1.z; acc[7]=c1.w;
    }
    #pragma unroll
    for (int k = 0; k < 4; k++) {
        int ss = s + k - 3;
        if (ss >= 0) {
            uint4 xv = *reinterpret_cast<const uint4*>(xbh + base + (ptrdiff_t)(k - 3) * D);
            const __half2* xp = reinterpret_cast<const __half2*>(&xv);
            float4 w0 = *reinterpret_cast<const float4*>(cw + k * D + d);
            float4 w1 = *reinterpret_cast<const float4*>(cw + k * D + d + 4);
            float2 p0 = __half22float2(xp[0]);
            float2 p1 = __half22float2(xp[1]);
            float2 p2 = __half22float2(xp[2]);
            float2 p3 = __half22float2(xp[3]);
            acc[0] = fmaf(w0.x, p0.x, acc[0]);
            acc[1] = fmaf(w0.y, p0.y, acc[1]);
            acc[2] = fmaf(w0.z, p1.x, acc[2]);
            acc[3] = fmaf(w0.w, p1.y, acc[3]);
            acc[4] = fmaf(w1.x, p2.x, acc[4]);
            acc[5] = fmaf(w1.y, p2.y, acc[5]);
            acc[6] = fmaf(w1.z, p3.x, acc[6]);
            acc[7] = fmaf(w1.w, p3.y, acc[7]);
        }
    }
    __half h8[8];
    #pragma unroll
    for (int j = 0; j < 8; j++) h8[j] = __float2half_rn(acc[j]);
    *reinterpret_cast<uint4*>(xcH + base) = *reinterpret_cast<uint4*>(h8);
}

// ---------------- scan pass2 ----------------
__global__ void scan_pass2(const float* __restrict__ hend, const float* __restrict__ aend,
                           const float* __restrict__ h0, float* __restrict__ carry,
                           float* __restrict__ hlast)
{
    using namespace hk;
    int ch = blockIdx.x * blockDim.x + threadIdx.x;
    if (ch >= B * D) return;
    int b = ch / D, d = ch % D;
    float cur = h0[ch];
    for (int c = 0; c < SC_NC; c++) {
        size_t o = ((size_t)b * SC_NC + c) * D + d;
        carry[o] = cur;
        cur = fmaf(aend[o], cur, hend[o]);
    }
    if (hlast) hlast[ch] = cur;
}

// ---------------- scan pass3 ----------------
__global__ void scan_pass3(const __half* __restrict__ omah, const __half* __restrict__ gbh,
                           const float* __restrict__ carry, const __half* __restrict__ yA,
                           __half* __restrict__ zA)
{
    using namespace hk;
    int t = blockIdx.x * blockDim.x + threadIdx.x;
    if (t >= B * SC_NC * D) return;
    int d = t % D;
    int c = (t / D) % SC_NC;
    int b = t / (D * SC_NC);
    float h = carry[((size_t)b * SC_NC + c) * D + d];
    size_t g = ((size_t)b * S + (size_t)c * SC_L) * D + d;
    for (int i = 0; i < SC_L; i++, g += D) {
        float a = 1.0f - __half2float(omah[g]);
        h = fmaf(a, h, __half2float(gbh[g]));
        zA[g] = __float2half_rn(__half2float(yA[g]) * h);
    }
}

// =====================================================================
// host-side tensormap encoding (driver symbol via dlsym)
// =====================================================================
typedef CUresult (*EncodeFn)(CUtensorMap*, CUtensorMapDataType, cuuint32_t, void*,
                             const cuuint64_t*, const cuuint64_t*, const cuuint32_t*,
                             const cuuint32_t*, CUtensorMapInterleave, CUtensorMapSwizzle,
                             CUtensorMapL2promotion, CUtensorMapFloatOOBfill);

static EncodeFn get_encode() {
    static EncodeFn fn = nullptr;
    if (!fn) {
        fn = (EncodeFn)dlsym(RTLD_DEFAULT, "cuTensorMapEncodeTiled");
        if (!fn) {
            void* h = dlopen("libcuda.so.1", RTLD_LAZY | RTLD_GLOBAL);
            if (h) fn = (EncodeFn)dlsym(h, "cuTensorMapEncodeTiled");
        }
    }
    return fn;
}

static void enc_map(CUtensorMap* m, void* ptr, uint64_t K, uint64_t ROWS, uint32_t boxRows) {
    cuuint64_t dims[2]    = {K, ROWS};
    cuuint64_t strides[1] = {K * 2};
    cuuint32_t box[2]     = {32, boxRows};
    cuuint32_t es[2]      = {1, 1};
    get_encode()(m, CU_TENSOR_MAP_DATA_TYPE_FLOAT16, 2, ptr, dims, strides, box, es,
                 CU_TENSOR_MAP_INTERLEAVE_NONE, CU_TENSOR_MAP_SWIZZLE_64B,
                 CU_TENSOR_MAP_L2_PROMOTION_L2_128B, CU_TENSOR_MAP_FLOAT_OOB_FILL_NONE);
}

// ---------------- launch ----------------
extern "C" void kernel_launch(void* const* d_in, const int* in_sizes, int n_in,
                              void* d_out, int out_size)
{
    using namespace hk;
    const float* x    = (const float*)d_in[0];
    const float* h0   = (const float*)d_in[1];
    const float* r1w  = (const float*)d_in[2];
    const float* r2w  = (const float*)d_in[3];
    const float* Wx   = (const float*)d_in[4];
    const float* Wy   = (const float*)d_in[5];
    const float* cw   = (const float*)d_in[6];
    const float* cb   = (const float*)d_in[7];
    const float* apar = (const float*)d_in[8];
    const float* igw  = (const float*)d_in[9];
    const float* igb  = (const float*)d_in[10];
    const float* agw  = (const float*)d_in[11];
    const float* agb  = (const float*)d_in[12];
    const float* Wout = (const float*)d_in[13];
    const float* Wg   = (const float*)d_in[14];
    const float* Wu   = (const float*)d_in[15];
    const float* Wd   = (const float*)d_in[16];
    float* out = (float*)d_out;

    float *resid, *hend, *aend, *carry;
    cudaGetSymbolAddress((void**)&resid, g_resid);
    cudaGetSymbolAddress((void**)&hend,  g_hend);
    cudaGetSymbolAddress((void**)&aend,  g_aend);
    cudaGetSymbolAddress((void**)&carry, g_carry);

    __half *omah,*gbh,*nA,*yA,*xbh,*xcH,*zA,*n2A,*GA,*guA;
    __half *tWyx,*tWo,*tWg,*tWu,*tWd,*aWH,*iWH;
    cudaGetSymbolAddress((void**)&omah, g_omah);
    cudaGetSymbolAddress((void**)&gbh, g_gbh);
    cudaGetSymbolAddress((void**)&nA,  g_nA);
    cudaGetSymbolAddress((void**)&yA,  g_yA);
    cudaGetSymbolAddress((void**)&xbh, g_xbh);
    cudaGetSymbolAddress((void**)&xcH, g_xcH);
    cudaGetSymbolAddress((void**)&zA,  g_zA);
    cudaGetSymbolAddress((void**)&n2A, g_n2A);
    cudaGetSymbolAddress((void**)&GA,  g_GA);
    cudaGetSymbolAddress((void**)&guA, g_guA);
    cudaGetSymbolAddress((void**)&tWyx, g_Wyx);
    cudaGetSymbolAddress((void**)&tWo, g_Wo);  cudaGetSymbolAddress((void**)&tWg, g_Wg);
    cudaGetSymbolAddress((void**)&tWu, g_Wu);  cudaGetSymbolAddress((void**)&tWd, g_Wd);
    cudaGetSymbolAddress((void**)&aWH, g_aWH); cudaGetSymbolAddress((void**)&iWH, g_iWH);

    // ---- tensormaps ----
    static CUtensorMap mnA, mzA, mn2A, mguA;
    static CUtensorMap mWyx, mWo, mWg, mWu, mWd;
    static CUtensorMap mXh, mWaH, mWiH;
    enc_map(&mnA,  nA,  D, BS, 128);
    enc_map(&mzA,  zA,  D, BS, 128);
    enc_map(&mn2A, n2A, D, BS, 128);
    enc_map(&mguA, guA, F, BS, 128);
    enc_map(&mWyx, tWyx, D, 2 * (uint64_t)D, 256);
    enc_map(&mWo,  tWo, D, D, 256);   enc_map(&mWg,  tWg, D, F, 256);
    enc_map(&mWu,  tWu, D, F, 256);   enc_map(&mWd,  tWd, F, D, 256);
    enc_map(&mXh,  xcH, D, BS, 128);
    enc_map(&mWaH, aWH, HD, (uint64_t)H * HD, 128);
    enc_map(&mWiH, iWH, HD, (uint64_t)H * HD, 128);

    cudaFuncSetAttribute(gemm_tma<2>, cudaFuncAttributeMaxDynamicSharedMemorySize, GT_SMEM);
    cudaFuncSetAttribute(gemm_tma<3>, cudaFuncAttributeMaxDynamicSharedMemorySize, GT_SMEM);
    cudaFuncSetAttribute(gemm_tma<4>, cudaFuncAttributeMaxDynamicSharedMemorySize, GT_SMEM);
    cudaFuncSetAttribute(gemm_dual,   cudaFuncAttributeMaxDynamicSharedMemorySize, GT_SMEM);
    cudaFuncSetAttribute(gate_mma,    cudaFuncAttributeMaxDynamicSharedMemorySize, GG_SMEM);

    float* hlast = (out_size >= (int)(NBSD + (size_t)B * D)) ? (out + NBSD) : nullptr;

    // ---- weight transpose/convert ----
    trans_all<<<15360, 256>>>(Wy, tWyx, Wx, tWyx + NDD, Wout, tWo,
                              Wg, tWg, Wu, tWu, Wd, tWd);
    trans_gate2<<<dim3(HD / 32, HD / 32, 2 * H), dim3(32, 8)>>>(agw, aWH, igw, iWH);

    // ---- temporal pre-norm (vectorized) ----
    rmsnorm_v<<<BS, 256>>>(x, r1w, nA);

    // ---- combined: y = gelu(nA @ Wy) fp16 AND xb = nA @ Wx fp16 ----
    dim3 gDual(2 * D / 256, BS / 128);
    gemm_dual<<<gDual, GT_THR, GT_SMEM>>>(mnA, mWyx, yA, xbh, D, D);

    // ---- causal conv (vectorized) ----
    conv_v<<<(unsigned)(NBSD / 8 / 256), 256>>>(xbh, cw, cb, xcH);

    // ---- fused gate GEMM + gate math + chunk-end scan ----
    gate_mma<<<dim3(BS / 128, H), 256, GG_SMEM>>>(mXh, mWaH, mWiH,
                                                  agb, igb, apar, omah, gbh, hend, aend);

    // ---- carries + final rescan fused with y-mul ----
    scan_pass2<<<(B * D + 255) / 256, 256>>>(hend, aend, h0, carry, hlast);
    scan_pass3<<<(B * SC_NC * D + 255) / 256, 256>>>(omah, gbh, carry, yA, zA);

    // ---- residual = z @ W_out + x ----
    dim3 gDD(D / 256, BS / 128);
    gemm_tma<2><<<gDD, GT_THR, GT_SMEM>>>(mzA, mWo, resid, x, nullptr, nullptr, D, D);

    // ---- second norm (vectorized) ----
    rmsnorm_v<<<BS, 256>>>(resid, r2w, n2A);

    // ---- MLP: G = gelu(n2 @ Wg) fp16; gu = (n2 @ Wu) * G fp16 ----
    dim3 gDF(F / 256, BS / 128);
    gemm_tma<4><<<gDF, GT_THR, GT_SMEM>>>(mn2A, mWg, nullptr, nullptr, nullptr, GA, F, D);
    gemm_tma<3><<<gDF, GT_THR, GT_SMEM>>>(mn2A, mWu, nullptr, nullptr, GA, guA, F, D);

    // ---- out = gu @ W_down + residual ----
    gemm_tma<2><<<gDD, GT_THR, GT_SMEM>>>(mguA, mWd, out, resid, nullptr, nullptr, D, F);
}